// round 1
// baseline (speedup 1.0000x reference)
#include <cuda_runtime.h>
#include <cuda_bf16.h>
#include <cstdio>

// Problem constants
#define BB    2
#define LL    2048
#define DIM   1024
#define DM    512
#define DI    1024
#define E2    2048      // 2*DI
#define MROWS 4096      // BB*LL
#define DS    16        // D_STATE
#define DTR   32        // DT_RANK
#define NC    16        // scan chunks
#define LC    128       // chunk length (NC*LC == LL)

// ---------------- scratch (static device memory; no allocation allowed) ----------
__device__ float g_xz   [2][MROWS * E2];       // in-proj output (xh | z)
__device__ float g_xc   [2][MROWS * DI];       // conv+silu output
__device__ float g_dbc  [2][MROWS * 64];       // x-proj output (dt|B|C)
__device__ float g_delta[2][MROWS * DI];       // softplus(dt @ dt_w^T + dt_b)
__device__ float g_ym   [2][MROWS * DI];       // scan output, gated
__device__ float g_cs   [2][BB * NC * DI];            // per-chunk sum of delta
__device__ float g_he   [2][BB * NC * DI * DS];       // chunk-local h_end
__device__ float g_hs   [2][BB * NC * DI * DS];       // chunk h_start (after fixup)

// ---------------- generic NT GEMM: C[m,n] = sum_k A[m,k] * W[n,k] -----------------
// A rows can be time-flipped per batch (for the backward direction input).
template<int BM, int BN, int BK, int TM, int TN>
__global__ void gemm_nt_kernel(const float* __restrict__ A,
                               const float* __restrict__ W,
                               float* __restrict__ C,
                               int Kdim,
                               int lda, int acol0, int flip,
                               int ldw, int ldc, int ccol0)
{
    constexpr int THREADS = (BM / TM) * (BN / TN);
    __shared__ float As[BK][BM];
    __shared__ float Ws[BK][BN];

    const int tid = threadIdx.x;
    const int bm0 = blockIdx.y * BM;
    const int bn0 = blockIdx.x * BN;
    const int tn  = tid % (BN / TN);
    const int tm  = tid / (BN / TN);

    float acc[TM][TN];
#pragma unroll
    for (int i = 0; i < TM; i++)
#pragma unroll
        for (int j = 0; j < TN; j++) acc[i][j] = 0.f;

    for (int k0 = 0; k0 < Kdim; k0 += BK) {
        // load A tile (BM x BK), float4 along k
        for (int i = tid * 4; i < BM * BK; i += THREADS * 4) {
            int mm = i / BK;
            int kk = i % BK;
            int mg = bm0 + mm;
            int row = mg;
            if (flip) {
                int b = mg >> 11;          // /LL
                int l = mg & (LL - 1);
                row = (b << 11) + (LL - 1 - l);
            }
            float4 v = *reinterpret_cast<const float4*>(&A[(long)row * lda + acol0 + k0 + kk]);
            As[kk + 0][mm] = v.x;
            As[kk + 1][mm] = v.y;
            As[kk + 2][mm] = v.z;
            As[kk + 3][mm] = v.w;
        }
        // load W tile (BN x BK)
        for (int i = tid * 4; i < BN * BK; i += THREADS * 4) {
            int nn = i / BK;
            int kk = i % BK;
            float4 v = *reinterpret_cast<const float4*>(&W[(long)(bn0 + nn) * ldw + k0 + kk]);
            Ws[kk + 0][nn] = v.x;
            Ws[kk + 1][nn] = v.y;
            Ws[kk + 2][nn] = v.z;
            Ws[kk + 3][nn] = v.w;
        }
        __syncthreads();

#pragma unroll
        for (int kk = 0; kk < BK; kk++) {
            float ar[TM], br[TN];
#pragma unroll
            for (int i = 0; i < TM; i++) ar[i] = As[kk][tm * TM + i];
#pragma unroll
            for (int j = 0; j < TN; j++) br[j] = Ws[kk][tn * TN + j];
#pragma unroll
            for (int i = 0; i < TM; i++)
#pragma unroll
                for (int j = 0; j < TN; j++) acc[i][j] = fmaf(ar[i], br[j], acc[i][j]);
        }
        __syncthreads();
    }

#pragma unroll
    for (int i = 0; i < TM; i++) {
        int m = bm0 + tm * TM + i;
#pragma unroll
        for (int j = 0; j < TN; j++) {
            int n = bn0 + tn * TN + j;
            C[(long)m * ldc + ccol0 + n] = acc[i][j];
        }
    }
}

// ---------------- depthwise causal conv(4) + silu ---------------------------------
__global__ void conv_silu_kernel(const float* __restrict__ xz,
                                 const float* __restrict__ cw,
                                 const float* __restrict__ cb,
                                 float* __restrict__ xc)
{
    int c  = blockIdx.x * blockDim.x + threadIdx.x;   // channel in [0,DI)
    int l0 = blockIdx.y * 8;
    int b  = blockIdx.z;

    float w0 = cw[c * 4 + 0], w1 = cw[c * 4 + 1], w2 = cw[c * 4 + 2], w3 = cw[c * 4 + 3];
    float bias = cb[c];

    float v[11];
#pragma unroll
    for (int j = 0; j < 11; j++) {
        int l = l0 - 3 + j;
        v[j] = (l >= 0) ? xz[(long)(b * LL + l) * E2 + c] : 0.f;
    }
#pragma unroll
    for (int i = 0; i < 8; i++) {
        float a = v[i] * w0 + v[i + 1] * w1 + v[i + 2] * w2 + v[i + 3] * w3 + bias;
        float s = a / (1.f + __expf(-a));   // silu
        xc[(long)(b * LL + l0 + i) * DI + c] = s;
    }
}

// ---------------- delta = softplus(dt @ dt_w^T + dt_b) ---------------------------
__global__ void delta_kernel(const float* __restrict__ dbc,
                             const float* __restrict__ dt_w,
                             const float* __restrict__ dt_b,
                             float* __restrict__ delta)
{
    int d  = blockIdx.x * 256 + threadIdx.x;  // [0,DI)
    int m0 = blockIdx.y * 4;

    float w[DTR];
    const float4* w4 = reinterpret_cast<const float4*>(dt_w + (long)d * DTR);
#pragma unroll
    for (int r = 0; r < DTR / 4; r++) {
        float4 v = w4[r];
        w[4 * r + 0] = v.x; w[4 * r + 1] = v.y; w[4 * r + 2] = v.z; w[4 * r + 3] = v.w;
    }
    float bias = dt_b[d];

#pragma unroll
    for (int mi = 0; mi < 4; mi++) {
        const float* row = dbc + (long)(m0 + mi) * 64;
        float acc = bias;
#pragma unroll
        for (int r = 0; r < DTR; r++) acc = fmaf(row[r], w[r], acc);
        float sp = (acc > 20.f) ? acc : log1pf(__expf(acc));
        delta[(long)(m0 + mi) * DI + d] = sp;
    }
}

// ---------------- scan pass1: chunk-local scan from h=0, record summary -----------
__global__ void scan_pass1_kernel(const float* __restrict__ delta,
                                  const float* __restrict__ xc,
                                  const float* __restrict__ dbc,
                                  const float* __restrict__ A_log,
                                  float* __restrict__ cs,
                                  float* __restrict__ he)
{
    __shared__ float sB[LC][DS];
    int chunk = blockIdx.x;
    int d     = blockIdx.y * 256 + threadIdx.x;
    int b     = blockIdx.z;
    int m0    = b * LL + chunk * LC;

    // stage B(t,s) for this chunk
    const float* dbc0 = dbc + (long)m0 * 64;
    for (int i = threadIdx.x; i < LC * DS; i += 256) {
        int t = i >> 4, s = i & 15;
        sB[t][s] = dbc0[t * 64 + 32 + s];
    }
    __syncthreads();

    float Aa[DS];
#pragma unroll
    for (int s = 0; s < DS; s++) Aa[s] = -__expf(A_log[d * DS + s]);

    float h[DS];
#pragma unroll
    for (int s = 0; s < DS; s++) h[s] = 0.f;
    float S = 0.f;

    for (int t = 0; t < LC; t++) {
        int m = m0 + t;
        float dlt = delta[(long)m * DI + d];
        float xcv = xc[(long)m * DI + d];
        S += dlt;
        float du = dlt * xcv;
#pragma unroll
        for (int s = 0; s < DS; s++) {
            float da = __expf(dlt * Aa[s]);
            h[s] = fmaf(h[s], da, du * sB[t][s]);
        }
    }

    cs[(long)(b * NC + chunk) * DI + d] = S;
    float* hout = he + ((long)(b * NC + chunk) * DI + d) * DS;
#pragma unroll
    for (int s = 0; s < DS; s++) hout[s] = h[s];
}

// ---------------- scan fixup: sequential over the 16 chunks -----------------------
__global__ void scan_fixup_kernel(const float* __restrict__ cs,
                                  const float* __restrict__ he,
                                  const float* __restrict__ A_log,
                                  float* __restrict__ hs)
{
    int idx = blockIdx.x * 256 + threadIdx.x;      // BB*DI*DS threads
    int s = idx & 15;
    int d = (idx >> 4) & (DI - 1);
    int b = idx >> 14;

    float A = -__expf(A_log[d * DS + s]);
    float h = 0.f;
    for (int c = 0; c < NC; c++) {
        long base = ((long)(b * NC + c) * DI + d) * DS + s;
        hs[base] = h;
        float S = cs[(long)(b * NC + c) * DI + d];
        h = __expf(A * S) * h + he[base];
    }
}

// ---------------- scan pass3: replay with h_start, emit gated y -------------------
__global__ void scan_pass3_kernel(const float* __restrict__ delta,
                                  const float* __restrict__ xc,
                                  const float* __restrict__ dbc,
                                  const float* __restrict__ A_log,
                                  const float* __restrict__ hs,
                                  const float* __restrict__ Dp,
                                  const float* __restrict__ xz,
                                  float* __restrict__ ym)
{
    __shared__ float sB[LC][DS];
    __shared__ float sC[LC][DS];
    int chunk = blockIdx.x;
    int d     = blockIdx.y * 256 + threadIdx.x;
    int b     = blockIdx.z;
    int m0    = b * LL + chunk * LC;

    const float* dbc0 = dbc + (long)m0 * 64;
    for (int i = threadIdx.x; i < LC * DS; i += 256) {
        int t = i >> 4, s = i & 15;
        sB[t][s] = dbc0[t * 64 + 32 + s];
        sC[t][s] = dbc0[t * 64 + 48 + s];
    }
    __syncthreads();

    float Aa[DS];
#pragma unroll
    for (int s = 0; s < DS; s++) Aa[s] = -__expf(A_log[d * DS + s]);

    float h[DS];
    const float* hin = hs + ((long)(b * NC + chunk) * DI + d) * DS;
#pragma unroll
    for (int s = 0; s < DS; s++) h[s] = hin[s];

    float Dv = Dp[d];

    for (int t = 0; t < LC; t++) {
        int m = m0 + t;
        float dlt = delta[(long)m * DI + d];
        float xcv = xc[(long)m * DI + d];
        float du = dlt * xcv;
        float y = 0.f;
#pragma unroll
        for (int s = 0; s < DS; s++) {
            float da = __expf(dlt * Aa[s]);
            h[s] = fmaf(h[s], da, du * sB[t][s]);
            y = fmaf(h[s], sC[t][s], y);
        }
        float z = xz[(long)m * E2 + DI + d];
        float sil = z / (1.f + __expf(-z));
        ym[(long)m * DI + d] = (y + xcv * Dv) * sil;
    }
}

// ---------------- residual copy ---------------------------------------------------
__global__ void copy_kernel(const float* __restrict__ src, float* __restrict__ dst, int n4)
{
    int i = blockIdx.x * 256 + threadIdx.x;
    if (i < n4) reinterpret_cast<float4*>(dst)[i] = reinterpret_cast<const float4*>(src)[i];
}

// ---------------- host launcher ---------------------------------------------------
extern "C" void kernel_launch(void* const* d_in, const int* in_sizes, int n_in,
                              void* d_out, int out_size)
{
    const float* x = (const float*)d_in[0];
    float* out = (float*)d_out;

    float *xz_base, *xc_base, *dbc_base, *delta_base, *ym_base, *cs_base, *he_base, *hs_base;
    cudaGetSymbolAddress((void**)&xz_base,    g_xz);
    cudaGetSymbolAddress((void**)&xc_base,    g_xc);
    cudaGetSymbolAddress((void**)&dbc_base,   g_dbc);
    cudaGetSymbolAddress((void**)&delta_base, g_delta);
    cudaGetSymbolAddress((void**)&ym_base,    g_ym);
    cudaGetSymbolAddress((void**)&cs_base,    g_cs);
    cudaGetSymbolAddress((void**)&he_base,    g_he);
    cudaGetSymbolAddress((void**)&hs_base,    g_hs);

    const long HID = (long)MROWS * DIM;  // hidden element count (= residual count)

    // residual copy (second half of output)
    copy_kernel<<<(MROWS * DIM / 4 + 255) / 256, 256>>>(x, out + HID, MROWS * DIM / 4);

    for (int dir = 0; dir < 2; dir++) {
        const float* in_w    = (const float*)d_in[1 + dir * 9 + 0];
        const float* conv_w  = (const float*)d_in[1 + dir * 9 + 1];
        const float* conv_b  = (const float*)d_in[1 + dir * 9 + 2];
        const float* xproj_w = (const float*)d_in[1 + dir * 9 + 3];
        const float* dt_w    = (const float*)d_in[1 + dir * 9 + 4];
        const float* dt_b    = (const float*)d_in[1 + dir * 9 + 5];
        const float* A_log   = (const float*)d_in[1 + dir * 9 + 6];
        const float* Dp      = (const float*)d_in[1 + dir * 9 + 7];
        const float* out_w   = (const float*)d_in[1 + dir * 9 + 8];

        float* xz    = xz_base    + (long)dir * MROWS * E2;
        float* xc    = xc_base    + (long)dir * MROWS * DI;
        float* dbc   = dbc_base   + (long)dir * MROWS * 64;
        float* delta = delta_base + (long)dir * MROWS * DI;
        float* ym    = ym_base    + (long)dir * MROWS * DI;
        float* cs    = cs_base    + (long)dir * BB * NC * DI;
        float* he    = he_base    + (long)dir * BB * NC * DI * DS;
        float* hs    = hs_base    + (long)dir * BB * NC * DI * DS;

        // 1) xz = x_dir @ in_w^T    (M=4096, N=2048, K=512)
        gemm_nt_kernel<128, 128, 16, 8, 8><<<dim3(E2 / 128, MROWS / 128), 256>>>(
            x, in_w, xz, DM,
            /*lda*/ DIM, /*acol0*/ dir * DM, /*flip*/ dir,
            /*ldw*/ DM, /*ldc*/ E2, /*ccol0*/ 0);

        // 2) xc = silu(causal depthwise conv4(xh) + b)
        conv_silu_kernel<<<dim3(DI / 256, LL / 8, BB), 256>>>(xz, conv_w, conv_b, xc);

        // 3) dbc = xc @ xproj_w^T   (M=4096, N=64, K=1024)
        gemm_nt_kernel<128, 64, 16, 8, 4><<<dim3(1, MROWS / 128), 256>>>(
            xc, xproj_w, dbc, DI,
            DI, 0, 0, DI, 64, 0);

        // 4) delta = softplus(dt @ dt_w^T + dt_b)
        delta_kernel<<<dim3(DI / 256, MROWS / 4), 256>>>(dbc, dt_w, dt_b, delta);

        // 5-7) chunked parallel scan
        scan_pass1_kernel<<<dim3(NC, DI / 256, BB), 256>>>(delta, xc, dbc, A_log, cs, he);
        scan_fixup_kernel<<<(BB * DI * DS) / 256, 256>>>(cs, he, A_log, hs);
        scan_pass3_kernel<<<dim3(NC, DI / 256, BB), 256>>>(delta, xc, dbc, A_log, hs, Dp, xz, ym);

        // 8) hidden[:, :, dir*512 : dir*512+512] = ym @ out_w^T  (M=4096, N=512, K=1024)
        gemm_nt_kernel<128, 128, 16, 8, 8><<<dim3(DM / 128, MROWS / 128), 256>>>(
            ym, out_w, out, DI,
            DI, 0, 0, DI, DIM, dir * DM);
    }
}

// round 3
// speedup vs baseline: 2.0244x; 2.0244x over previous
#include <cuda_runtime.h>
#include <cuda_bf16.h>
#include <cstdint>

// Problem constants
#define BB    2
#define LL    2048
#define DIM   1024
#define DM    512
#define DI    1024
#define E2    2048      // 2*DI
#define MROWS 4096      // BB*LL
#define DS    16        // D_STATE
#define DTR   32        // DT_RANK
#define NC    16        // scan chunks
#define LC    128       // chunk length (NC*LC == LL)

// ---------------- scratch (static device memory; no allocation allowed) ----------
__device__ float g_xz   [2][MROWS * E2];       // in-proj output (xh | z)
__device__ float g_xc   [2][MROWS * DI];       // conv+silu output (fp32 for scan)
__device__ float g_dbc  [2][MROWS * 64];       // x-proj output (dt|B|C)
__device__ float g_delta[2][MROWS * DI];       // softplus(dt @ dt_w^T + dt_b)
__device__ float g_cs   [2][BB * NC * DI];            // per-chunk sum of delta
__device__ float g_he   [2][BB * NC * DI * DS];       // chunk-local h_end
__device__ float g_hs   [2][BB * NC * DI * DS];       // chunk h_start (after fixup)

// bf16 hi/lo split operands for tensor-core GEMMs
__device__ __nv_bfloat16 g_xbh [MROWS * DIM];
__device__ __nv_bfloat16 g_xbl [MROWS * DIM];
__device__ __nv_bfloat16 g_w1h [2][E2 * DM];
__device__ __nv_bfloat16 g_w1l [2][E2 * DM];
__device__ __nv_bfloat16 g_wxh [2][64 * DI];
__device__ __nv_bfloat16 g_wxl [2][64 * DI];
__device__ __nv_bfloat16 g_woh [2][DM * DI];
__device__ __nv_bfloat16 g_wol [2][DM * DI];
__device__ __nv_bfloat16 g_xch [2][MROWS * DI];
__device__ __nv_bfloat16 g_xcl [2][MROWS * DI];
__device__ __nv_bfloat16 g_ymh [2][MROWS * DI];
__device__ __nv_bfloat16 g_yml [2][MROWS * DI];

// ---------------- helpers ----------------------------------------------------------
__device__ __forceinline__ void split2(float v, __nv_bfloat16& h, __nv_bfloat16& l) {
    h = __float2bfloat16(v);
    l = __float2bfloat16(v - __bfloat162float(h));
}

__device__ __forceinline__ void mma_bf16(float* c, const uint32_t* a, const uint32_t* b) {
    asm volatile(
        "mma.sync.aligned.m16n8k16.row.col.f32.bf16.bf16.f32 "
        "{%0,%1,%2,%3}, {%4,%5,%6,%7}, {%8,%9}, {%0,%1,%2,%3};\n"
        : "+f"(c[0]), "+f"(c[1]), "+f"(c[2]), "+f"(c[3])
        : "r"(a[0]), "r"(a[1]), "r"(a[2]), "r"(a[3]), "r"(b[0]), "r"(b[1]));
}

#define CPASYNC16(dst, src) asm volatile("cp.async.cg.shared.global [%0], [%1], 16;\n" :: "r"(dst), "l"(src))
#define CPCOMMIT()          asm volatile("cp.async.commit_group;\n")
#define CPWAIT1()           asm volatile("cp.async.wait_group 1;\n")

__device__ __forceinline__ uint32_t smem_u32(const void* p) {
    return (uint32_t)__cvta_generic_to_shared(p);
}

// ---------------- split fp32 -> bf16 hi/lo (vectorized float4) ---------------------
__device__ __forceinline__ void split_body(const float* __restrict__ in,
                                           __nv_bfloat16* __restrict__ hi,
                                           __nv_bfloat16* __restrict__ lo, int i)
{
    float4 v = reinterpret_cast<const float4*>(in)[i];
    float vv[4] = {v.x, v.y, v.z, v.w};
    __nv_bfloat16 h[4], l[4];
#pragma unroll
    for (int k = 0; k < 4; k++) split2(vv[k], h[k], l[k]);
    __nv_bfloat162* hp = reinterpret_cast<__nv_bfloat162*>(hi) + 2 * i;
    __nv_bfloat162* lp = reinterpret_cast<__nv_bfloat162*>(lo) + 2 * i;
    __nv_bfloat162 t;
    t.x = h[0]; t.y = h[1]; hp[0] = t;
    t.x = h[2]; t.y = h[3]; hp[1] = t;
    t.x = l[0]; t.y = l[1]; lp[0] = t;
    t.x = l[2]; t.y = l[3]; lp[1] = t;
}

__global__ void split_kernel(const float* __restrict__ in,
                             __nv_bfloat16* __restrict__ hi,
                             __nv_bfloat16* __restrict__ lo, int n4)
{
    int i = blockIdx.x * 256 + threadIdx.x;
    if (i < n4) split_body(in, hi, lo, i);
}

// Fused per-direction weight splits (in_w | xproj_w | out_w), one launch.
__global__ void split_weights_kernel(const float* __restrict__ w1,
                                     __nv_bfloat16* __restrict__ w1h, __nv_bfloat16* __restrict__ w1l,
                                     const float* __restrict__ wx,
                                     __nv_bfloat16* __restrict__ wxh, __nv_bfloat16* __restrict__ wxl,
                                     const float* __restrict__ wo,
                                     __nv_bfloat16* __restrict__ woh, __nv_bfloat16* __restrict__ wol)
{
    const int N1 = E2 * DM / 4;      // 262144
    const int N2 = 64 * DI / 4;      // 16384
    const int N3 = DM * DI / 4;      // 131072
    int i = blockIdx.x * 256 + threadIdx.x;
    if (i < N1) { split_body(w1, w1h, w1l, i); return; }
    i -= N1;
    if (i < N2) { split_body(wx, wxh, wxl, i); return; }
    i -= N2;
    if (i < N3) { split_body(wo, woh, wol, i); }
}

// ---------------- tensor-core NT GEMM with 3-term bf16 split ------------------------
// C[m,n] = sum_k A[m,k] * W[n,k], fp32-accurate via Ahi*Bhi + Ahi*Blo + Alo*Bhi.
// smem tile layout: [rows][16 halves]; 16B chunk swizzle: phys = chunk ^ ((r>>2)&1).
template<int BM, int BN, int WM, int WN>
__global__ void __launch_bounds__((BM / WM) * (BN / WN) * 32)
mma_gemm_kernel(const __nv_bfloat16* __restrict__ Ahi, const __nv_bfloat16* __restrict__ Alo,
                const __nv_bfloat16* __restrict__ Bhi, const __nv_bfloat16* __restrict__ Blo,
                float* __restrict__ C, int K,
                int lda, int acol0, int flip,
                int ldb, int ldc, int ccol0)
{
    constexpr int THREADS = (BM / WM) * (BN / WN) * 32;
    constexpr int WM16 = WM / 16;
    constexpr int WN8  = WN / 8;

    __shared__ __align__(16) uint8_t As[2 * 2 * BM * 32];   // [stage][comp][BM][32B]
    __shared__ __align__(16) uint8_t Bs[2 * 2 * BN * 32];

    const int tid = threadIdx.x;
    const int bm0 = blockIdx.y * BM;
    const int bn0 = blockIdx.x * BN;
    const int KT  = K / 16;

    const int wid  = tid >> 5;
    const int lane = tid & 31;
    const int wm   = wid / (BN / WN);
    const int wn   = wid % (BN / WN);
    const int g    = lane >> 2;
    const int t    = lane & 3;

    float acc[WM16][WN8][4];
#pragma unroll
    for (int i = 0; i < WM16; i++)
#pragma unroll
        for (int j = 0; j < WN8; j++)
#pragma unroll
            for (int q = 0; q < 4; q++) acc[i][j][q] = 0.f;

    auto loadA = [&](int st, int k0) {
        for (int i = tid; i < BM * 4; i += THREADS) {
            int comp = i / (BM * 2);
            int rem  = i - comp * BM * 2;
            int r = rem >> 1;
            int c = rem & 1;
            int mg = bm0 + r;
            int rowg = mg;
            if (flip) { int b = mg >> 11; int l = mg & 2047; rowg = (b << 11) + (2047 - l); }
            const __nv_bfloat16* src = (comp ? Alo : Ahi) + (long)rowg * lda + acol0 + k0 + c * 8;
            uint32_t dst = smem_u32(As + ((st * 2 + comp) * BM + r) * 32 + ((c ^ ((r >> 2) & 1)) << 4));
            CPASYNC16(dst, src);
        }
    };
    auto loadB = [&](int st, int k0) {
        for (int i = tid; i < BN * 4; i += THREADS) {
            int comp = i / (BN * 2);
            int rem  = i - comp * BN * 2;
            int r = rem >> 1;
            int c = rem & 1;
            const __nv_bfloat16* src = (comp ? Blo : Bhi) + (long)(bn0 + r) * ldb + k0 + c * 8;
            uint32_t dst = smem_u32(Bs + ((st * 2 + comp) * BN + r) * 32 + ((c ^ ((r >> 2) & 1)) << 4));
            CPASYNC16(dst, src);
        }
    };

    auto ld32 = [&](const uint8_t* base, int r, int k) -> uint32_t {
        return *reinterpret_cast<const uint32_t*>(
            base + r * 32 + ((((k >> 3) ^ ((r >> 2) & 1))) << 4) + ((k & 7) << 1));
    };

    loadA(0, 0); loadB(0, 0); CPCOMMIT();

    for (int kt = 0; kt < KT; kt++) {
        if (kt + 1 < KT) { loadA((kt + 1) & 1, (kt + 1) * 16); loadB((kt + 1) & 1, (kt + 1) * 16); }
        CPCOMMIT();
        CPWAIT1();
        __syncthreads();

        const int st = kt & 1;
        const uint8_t* Ah = As + (st * 2 + 0) * BM * 32;
        const uint8_t* Al = As + (st * 2 + 1) * BM * 32;
        const uint8_t* Bh = Bs + (st * 2 + 0) * BN * 32;
        const uint8_t* Bl = Bs + (st * 2 + 1) * BN * 32;

        uint32_t ah[WM16][4], al[WM16][4], bh[WN8][2], bl[WN8][2];
#pragma unroll
        for (int i = 0; i < WM16; i++) {
            int r0 = wm * WM + i * 16;
            ah[i][0] = ld32(Ah, r0 + g,     2 * t);
            ah[i][1] = ld32(Ah, r0 + 8 + g, 2 * t);
            ah[i][2] = ld32(Ah, r0 + g,     8 + 2 * t);
            ah[i][3] = ld32(Ah, r0 + 8 + g, 8 + 2 * t);
            al[i][0] = ld32(Al, r0 + g,     2 * t);
            al[i][1] = ld32(Al, r0 + 8 + g, 2 * t);
            al[i][2] = ld32(Al, r0 + g,     8 + 2 * t);
            al[i][3] = ld32(Al, r0 + 8 + g, 8 + 2 * t);
        }
#pragma unroll
        for (int j = 0; j < WN8; j++) {
            int n0 = wn * WN + j * 8;
            bh[j][0] = ld32(Bh, n0 + g, 2 * t);
            bh[j][1] = ld32(Bh, n0 + g, 8 + 2 * t);
            bl[j][0] = ld32(Bl, n0 + g, 2 * t);
            bl[j][1] = ld32(Bl, n0 + g, 8 + 2 * t);
        }
#pragma unroll
        for (int i = 0; i < WM16; i++)
#pragma unroll
            for (int j = 0; j < WN8; j++) {
                mma_bf16(acc[i][j], ah[i], bh[j]);
                mma_bf16(acc[i][j], ah[i], bl[j]);
                mma_bf16(acc[i][j], al[i], bh[j]);
            }
        __syncthreads();
    }

    // epilogue: fp32 direct store (cols 2t,2t+1 contiguous -> float2)
#pragma unroll
    for (int i = 0; i < WM16; i++) {
#pragma unroll
        for (int j = 0; j < WN8; j++) {
            int r  = bm0 + wm * WM + i * 16 + g;
            int n0 = bn0 + ccol0 + wn * WN + j * 8 + 2 * t;
            float2 v0 = make_float2(acc[i][j][0], acc[i][j][1]);
            float2 v1 = make_float2(acc[i][j][2], acc[i][j][3]);
            *reinterpret_cast<float2*>(&C[(long)r * ldc + n0])       = v0;
            *reinterpret_cast<float2*>(&C[(long)(r + 8) * ldc + n0]) = v1;
        }
    }
}

// ---------------- depthwise causal conv(4) + silu (+ bf16 split out) ---------------
__global__ void conv_silu_kernel(const float* __restrict__ xz,
                                 const float* __restrict__ cw,
                                 const float* __restrict__ cb,
                                 float* __restrict__ xc,
                                 __nv_bfloat16* __restrict__ xch,
                                 __nv_bfloat16* __restrict__ xcl)
{
    int c  = blockIdx.x * blockDim.x + threadIdx.x;   // channel in [0,DI)
    int l0 = blockIdx.y * 8;
    int b  = blockIdx.z;

    float w0 = cw[c * 4 + 0], w1 = cw[c * 4 + 1], w2 = cw[c * 4 + 2], w3 = cw[c * 4 + 3];
    float bias = cb[c];

    float v[11];
#pragma unroll
    for (int j = 0; j < 11; j++) {
        int l = l0 - 3 + j;
        v[j] = (l >= 0) ? xz[(long)(b * LL + l) * E2 + c] : 0.f;
    }
#pragma unroll
    for (int i = 0; i < 8; i++) {
        float a = v[i] * w0 + v[i + 1] * w1 + v[i + 2] * w2 + v[i + 3] * w3 + bias;
        float s = a / (1.f + __expf(-a));   // silu
        long idx = (long)(b * LL + l0 + i) * DI + c;
        xc[idx] = s;
        __nv_bfloat16 h, l2;
        split2(s, h, l2);
        xch[idx] = h;
        xcl[idx] = l2;
    }
}

// ---------------- delta = softplus(dt @ dt_w^T + dt_b) ---------------------------
__global__ void delta_kernel(const float* __restrict__ dbc,
                             const float* __restrict__ dt_w,
                             const float* __restrict__ dt_b,
                             float* __restrict__ delta)
{
    int d  = blockIdx.x * 256 + threadIdx.x;  // [0,DI)
    int m0 = blockIdx.y * 4;

    float w[DTR];
    const float4* w4 = reinterpret_cast<const float4*>(dt_w + (long)d * DTR);
#pragma unroll
    for (int r = 0; r < DTR / 4; r++) {
        float4 v = w4[r];
        w[4 * r + 0] = v.x; w[4 * r + 1] = v.y; w[4 * r + 2] = v.z; w[4 * r + 3] = v.w;
    }
    float bias = dt_b[d];

#pragma unroll
    for (int mi = 0; mi < 4; mi++) {
        const float* row = dbc + (long)(m0 + mi) * 64;
        float acc = bias;
#pragma unroll
        for (int r = 0; r < DTR; r++) acc = fmaf(row[r], w[r], acc);
        float sp = (acc > 20.f) ? acc : log1pf(__expf(acc));
        delta[(long)(m0 + mi) * DI + d] = sp;
    }
}

// ---------------- scan pass1: chunk-local scan from h=0, record summary -----------
__global__ void scan_pass1_kernel(const float* __restrict__ delta,
                                  const float* __restrict__ xc,
                                  const float* __restrict__ dbc,
                                  const float* __restrict__ A_log,
                                  float* __restrict__ cs,
                                  float* __restrict__ he)
{
    __shared__ float sB[LC][DS];
    int chunk = blockIdx.x;
    int d     = blockIdx.y * 256 + threadIdx.x;
    int b     = blockIdx.z;
    int m0    = b * LL + chunk * LC;

    const float* dbc0 = dbc + (long)m0 * 64;
    for (int i = threadIdx.x; i < LC * DS; i += 256) {
        int tt = i >> 4, s = i & 15;
        sB[tt][s] = dbc0[tt * 64 + 32 + s];
    }
    __syncthreads();

    float Aa[DS];
#pragma unroll
    for (int s = 0; s < DS; s++) Aa[s] = -__expf(A_log[d * DS + s]);
    float a0 = Aa[0];
    bool fast = true;
#pragma unroll
    for (int s = 1; s < DS; s++) fast = fast && (fabsf(Aa[s] - (s + 1) * a0) < 1e-4f * fabsf(Aa[s]));

    float h[DS];
#pragma unroll
    for (int s = 0; s < DS; s++) h[s] = 0.f;
    float S = 0.f;

    if (fast) {
        for (int tt = 0; tt < LC; tt++) {
            int m = m0 + tt;
            float dlt = delta[(long)m * DI + d];
            float xcv = xc[(long)m * DI + d];
            S += dlt;
            float du = dlt * xcv;
            float e1 = __expf(dlt * a0);
            float p = e1;
#pragma unroll
            for (int s = 0; s < DS; s++) {
                h[s] = fmaf(h[s], p, du * sB[tt][s]);
                p *= e1;
            }
        }
    } else {
        for (int tt = 0; tt < LC; tt++) {
            int m = m0 + tt;
            float dlt = delta[(long)m * DI + d];
            float xcv = xc[(long)m * DI + d];
            S += dlt;
            float du = dlt * xcv;
#pragma unroll
            for (int s = 0; s < DS; s++) {
                float da = __expf(dlt * Aa[s]);
                h[s] = fmaf(h[s], da, du * sB[tt][s]);
            }
        }
    }

    cs[(long)(b * NC + chunk) * DI + d] = S;
    float* hout = he + ((long)(b * NC + chunk) * DI + d) * DS;
#pragma unroll
    for (int s = 0; s < DS; s++) hout[s] = h[s];
}

// ---------------- scan fixup: sequential over the 16 chunks -----------------------
__global__ void scan_fixup_kernel(const float* __restrict__ cs,
                                  const float* __restrict__ he,
                                  const float* __restrict__ A_log,
                                  float* __restrict__ hs)
{
    int idx = blockIdx.x * 256 + threadIdx.x;      // BB*DI*DS threads
    int s = idx & 15;
    int d = (idx >> 4) & (DI - 1);
    int b = idx >> 14;

    float A = -__expf(A_log[d * DS + s]);
    float h = 0.f;
    for (int c = 0; c < NC; c++) {
        long base = ((long)(b * NC + c) * DI + d) * DS + s;
        hs[base] = h;
        float S = cs[(long)(b * NC + c) * DI + d];
        h = __expf(A * S) * h + he[base];
    }
}

// ---------------- scan pass3: replay with h_start, emit gated y (bf16 hi/lo) ------
__global__ void scan_pass3_kernel(const float* __restrict__ delta,
                                  const float* __restrict__ xc,
                                  const float* __restrict__ dbc,
                                  const float* __restrict__ A_log,
                                  const float* __restrict__ hs,
                                  const float* __restrict__ Dp,
                                  const float* __restrict__ xz,
                                  __nv_bfloat16* __restrict__ ymh,
                                  __nv_bfloat16* __restrict__ yml)
{
    __shared__ float sB[LC][DS];
    __shared__ float sC[LC][DS];
    int chunk = blockIdx.x;
    int d     = blockIdx.y * 256 + threadIdx.x;
    int b     = blockIdx.z;
    int m0    = b * LL + chunk * LC;

    const float* dbc0 = dbc + (long)m0 * 64;
    for (int i = threadIdx.x; i < LC * DS; i += 256) {
        int tt = i >> 4, s = i & 15;
        sB[tt][s] = dbc0[tt * 64 + 32 + s];
        sC[tt][s] = dbc0[tt * 64 + 48 + s];
    }
    __syncthreads();

    float Aa[DS];
#pragma unroll
    for (int s = 0; s < DS; s++) Aa[s] = -__expf(A_log[d * DS + s]);
    float a0 = Aa[0];
    bool fast = true;
#pragma unroll
    for (int s = 1; s < DS; s++) fast = fast && (fabsf(Aa[s] - (s + 1) * a0) < 1e-4f * fabsf(Aa[s]));

    float h[DS];
    const float* hin = hs + ((long)(b * NC + chunk) * DI + d) * DS;
#pragma unroll
    for (int s = 0; s < DS; s++) h[s] = hin[s];

    float Dv = Dp[d];

    for (int tt = 0; tt < LC; tt++) {
        int m = m0 + tt;
        float dlt = delta[(long)m * DI + d];
        float xcv = xc[(long)m * DI + d];
        float du = dlt * xcv;
        float y = 0.f;
        if (fast) {
            float e1 = __expf(dlt * a0);
            float p = e1;
#pragma unroll
            for (int s = 0; s < DS; s++) {
                h[s] = fmaf(h[s], p, du * sB[tt][s]);
                y = fmaf(h[s], sC[tt][s], y);
                p *= e1;
            }
        } else {
#pragma unroll
            for (int s = 0; s < DS; s++) {
                float da = __expf(dlt * Aa[s]);
                h[s] = fmaf(h[s], da, du * sB[tt][s]);
                y = fmaf(h[s], sC[tt][s], y);
            }
        }
        float z = xz[(long)m * E2 + DI + d];
        float sil = z / (1.f + __expf(-z));
        float out = (y + xcv * Dv) * sil;
        __nv_bfloat16 hh, ll;
        split2(out, hh, ll);
        long idx = (long)m * DI + d;
        ymh[idx] = hh;
        yml[idx] = ll;
    }
}

// ---------------- residual copy ---------------------------------------------------
__global__ void copy_kernel(const float* __restrict__ src, float* __restrict__ dst, int n4)
{
    int i = blockIdx.x * 256 + threadIdx.x;
    if (i < n4) reinterpret_cast<float4*>(dst)[i] = reinterpret_cast<const float4*>(src)[i];
}

// ---------------- host launcher ---------------------------------------------------
extern "C" void kernel_launch(void* const* d_in, const int* in_sizes, int n_in,
                              void* d_out, int out_size)
{
    const float* x = (const float*)d_in[0];
    float* out = (float*)d_out;

    float *xz_base, *xc_base, *dbc_base, *delta_base, *cs_base, *he_base, *hs_base;
    cudaGetSymbolAddress((void**)&xz_base,    g_xz);
    cudaGetSymbolAddress((void**)&xc_base,    g_xc);
    cudaGetSymbolAddress((void**)&dbc_base,   g_dbc);
    cudaGetSymbolAddress((void**)&delta_base, g_delta);
    cudaGetSymbolAddress((void**)&cs_base,    g_cs);
    cudaGetSymbolAddress((void**)&he_base,    g_he);
    cudaGetSymbolAddress((void**)&hs_base,    g_hs);

    __nv_bfloat16 *xbh, *xbl, *w1h, *w1l, *wxh, *wxl, *woh, *wol, *xch, *xcl, *ymh, *yml;
    cudaGetSymbolAddress((void**)&xbh, g_xbh);
    cudaGetSymbolAddress((void**)&xbl, g_xbl);
    cudaGetSymbolAddress((void**)&w1h, g_w1h);
    cudaGetSymbolAddress((void**)&w1l, g_w1l);
    cudaGetSymbolAddress((void**)&wxh, g_wxh);
    cudaGetSymbolAddress((void**)&wxl, g_wxl);
    cudaGetSymbolAddress((void**)&woh, g_woh);
    cudaGetSymbolAddress((void**)&wol, g_wol);
    cudaGetSymbolAddress((void**)&xch, g_xch);
    cudaGetSymbolAddress((void**)&xcl, g_xcl);
    cudaGetSymbolAddress((void**)&ymh, g_ymh);
    cudaGetSymbolAddress((void**)&yml, g_yml);

    const long HID = (long)MROWS * DIM;

    // residual copy (second half of output)
    copy_kernel<<<(MROWS * DIM / 4 + 255) / 256, 256>>>(x, out + HID, MROWS * DIM / 4);

    // split x -> bf16 hi/lo (shared by both directions)
    split_kernel<<<(MROWS * DIM / 4 + 255) / 256, 256>>>(x, xbh, xbl, MROWS * DIM / 4);

    const int NW = (E2 * DM / 4) + (64 * DI / 4) + (DM * DI / 4);

    for (int dir = 0; dir < 2; dir++) {
        const float* in_w    = (const float*)d_in[1 + dir * 9 + 0];
        const float* conv_w  = (const float*)d_in[1 + dir * 9 + 1];
        const float* conv_b  = (const float*)d_in[1 + dir * 9 + 2];
        const float* xproj_w = (const float*)d_in[1 + dir * 9 + 3];
        const float* dt_w    = (const float*)d_in[1 + dir * 9 + 4];
        const float* dt_b    = (const float*)d_in[1 + dir * 9 + 5];
        const float* A_log   = (const float*)d_in[1 + dir * 9 + 6];
        const float* Dp      = (const float*)d_in[1 + dir * 9 + 7];
        const float* out_w   = (const float*)d_in[1 + dir * 9 + 8];

        float* xz    = xz_base    + (long)dir * MROWS * E2;
        float* xc    = xc_base    + (long)dir * MROWS * DI;
        float* dbc   = dbc_base   + (long)dir * MROWS * 64;
        float* delta = delta_base + (long)dir * MROWS * DI;
        float* cs    = cs_base    + (long)dir * BB * NC * DI;
        float* he    = he_base    + (long)dir * BB * NC * DI * DS;
        float* hs    = hs_base    + (long)dir * BB * NC * DI * DS;

        __nv_bfloat16* w1h_d = w1h + (long)dir * E2 * DM;
        __nv_bfloat16* w1l_d = w1l + (long)dir * E2 * DM;
        __nv_bfloat16* wxh_d = wxh + (long)dir * 64 * DI;
        __nv_bfloat16* wxl_d = wxl + (long)dir * 64 * DI;
        __nv_bfloat16* woh_d = woh + (long)dir * DM * DI;
        __nv_bfloat16* wol_d = wol + (long)dir * DM * DI;
        __nv_bfloat16* xch_d = xch + (long)dir * MROWS * DI;
        __nv_bfloat16* xcl_d = xcl + (long)dir * MROWS * DI;
        __nv_bfloat16* ymh_d = ymh + (long)dir * MROWS * DI;
        __nv_bfloat16* yml_d = yml + (long)dir * MROWS * DI;

        // fused weight splits (one launch per direction)
        split_weights_kernel<<<(NW + 255) / 256, 256>>>(
            in_w, w1h_d, w1l_d, xproj_w, wxh_d, wxl_d, out_w, woh_d, wol_d);

        // 1) xz = x_dir @ in_w^T    (M=4096, N=2048, K=512), tensor cores
        mma_gemm_kernel<128, 128, 64, 32><<<dim3(E2 / 128, MROWS / 128), 256>>>(
            xbh, xbl, w1h_d, w1l_d, xz, DM,
            /*lda*/ DIM, /*acol0*/ dir * DM, /*flip*/ dir,
            /*ldb*/ DM, /*ldc*/ E2, /*ccol0*/ 0);

        // 2) xc = silu(causal depthwise conv4(xh) + b), emits fp32 + bf16 hi/lo
        conv_silu_kernel<<<dim3(DI / 256, LL / 8, BB), 256>>>(xz, conv_w, conv_b, xc, xch_d, xcl_d);

        // 3) dbc = xc @ xproj_w^T   (M=4096, N=64, K=1024)
        mma_gemm_kernel<64, 64, 32, 32><<<dim3(1, MROWS / 64), 128>>>(
            xch_d, xcl_d, wxh_d, wxl_d, dbc, DI,
            DI, 0, 0, DI, 64, 0);

        // 4) delta = softplus(dt @ dt_w^T + dt_b)
        delta_kernel<<<dim3(DI / 256, MROWS / 4), 256>>>(dbc, dt_w, dt_b, delta);

        // 5-7) chunked parallel scan
        scan_pass1_kernel<<<dim3(NC, DI / 256, BB), 256>>>(delta, xc, dbc, A_log, cs, he);
        scan_fixup_kernel<<<(BB * DI * DS) / 256, 256>>>(cs, he, A_log, hs);
        scan_pass3_kernel<<<dim3(NC, DI / 256, BB), 256>>>(delta, xc, dbc, A_log, hs, Dp, xz, ymh_d, yml_d);

        // 8) hidden[:, :, dir*512 : dir*512+512] = ym @ out_w^T  (M=4096, N=512, K=1024)
        mma_gemm_kernel<128, 128, 64, 32><<<dim3(DM / 128, MROWS / 128), 256>>>(
            ymh_d, yml_d, woh_d, wol_d, out, DI,
            DI, 0, 0, DI, DIM, dir * DM);
    }
}

// round 4
// speedup vs baseline: 2.1647x; 1.0693x over previous
#include <cuda_runtime.h>
#include <cuda_bf16.h>
#include <cstdint>

// Problem constants
#define BB    2
#define LL    2048
#define DIM   1024
#define DM    512
#define DI    1024
#define E2    2048      // 2*DI
#define MROWS 4096      // BB*LL
#define DS    16        // D_STATE
#define DTR   32        // DT_RANK
#define NC    16        // scan chunks
#define LC    128       // chunk length (NC*LC == LL)
#define KSPLIT 4        // split-K factor for xproj GEMM

// ---------------- scratch (static device memory; no allocation allowed) ----------
__device__ float g_xz   [2][MROWS * E2];       // in-proj output (xh | z)
__device__ float g_xc   [2][MROWS * DI];       // conv+silu output (fp32 for scan)
__device__ float g_dbc  [2][MROWS * 64];       // x-proj output (dt|B|C)
__device__ float g_part [KSPLIT][MROWS * 64];  // split-K partials for xproj
__device__ float g_delta[2][MROWS * DI];       // softplus(dt @ dt_w^T + dt_b)
__device__ float g_cs   [2][BB * NC * DI];            // per-chunk sum of delta
__device__ float g_he   [2][BB * NC * DI * DS];       // chunk-local h_end
__device__ float g_hs   [2][BB * NC * DI * DS];       // chunk h_start (after fixup)

// bf16 hi/lo split operands for tensor-core GEMMs
__device__ __nv_bfloat16 g_xbh [MROWS * DIM];
__device__ __nv_bfloat16 g_xbl [MROWS * DIM];
__device__ __nv_bfloat16 g_w1h [2][E2 * DM];
__device__ __nv_bfloat16 g_w1l [2][E2 * DM];
__device__ __nv_bfloat16 g_wxh [2][64 * DI];
__device__ __nv_bfloat16 g_wxl [2][64 * DI];
__device__ __nv_bfloat16 g_woh [2][DM * DI];
__device__ __nv_bfloat16 g_wol [2][DM * DI];
__device__ __nv_bfloat16 g_xch [2][MROWS * DI];
__device__ __nv_bfloat16 g_xcl [2][MROWS * DI];
__device__ __nv_bfloat16 g_ymh [2][MROWS * DI];
__device__ __nv_bfloat16 g_yml [2][MROWS * DI];

// ---------------- helpers ----------------------------------------------------------
__device__ __forceinline__ void split2(float v, __nv_bfloat16& h, __nv_bfloat16& l) {
    h = __float2bfloat16(v);
    l = __float2bfloat16(v - __bfloat162float(h));
}

__device__ __forceinline__ void mma_bf16(float* c, const uint32_t* a, const uint32_t* b) {
    asm volatile(
        "mma.sync.aligned.m16n8k16.row.col.f32.bf16.bf16.f32 "
        "{%0,%1,%2,%3}, {%4,%5,%6,%7}, {%8,%9}, {%0,%1,%2,%3};\n"
        : "+f"(c[0]), "+f"(c[1]), "+f"(c[2]), "+f"(c[3])
        : "r"(a[0]), "r"(a[1]), "r"(a[2]), "r"(a[3]), "r"(b[0]), "r"(b[1]));
}

__device__ __forceinline__ void ldsm_x4(uint32_t& r0, uint32_t& r1, uint32_t& r2, uint32_t& r3, uint32_t a) {
    asm volatile("ldmatrix.sync.aligned.m8n8.x4.shared.b16 {%0,%1,%2,%3}, [%4];"
                 : "=r"(r0), "=r"(r1), "=r"(r2), "=r"(r3) : "r"(a));
}

#define CPASYNC16(dst, src) asm volatile("cp.async.cg.shared.global [%0], [%1], 16;\n" :: "r"(dst), "l"(src))
#define CPCOMMIT()          asm volatile("cp.async.commit_group;\n")
#define CPWAIT1()           asm volatile("cp.async.wait_group 1;\n")

__device__ __forceinline__ uint32_t smem_u32(const void* p) {
    return (uint32_t)__cvta_generic_to_shared(p);
}

// ---------------- split fp32 -> bf16 hi/lo (vectorized float4) ---------------------
__device__ __forceinline__ void split_body(const float* __restrict__ in,
                                           __nv_bfloat16* __restrict__ hi,
                                           __nv_bfloat16* __restrict__ lo, int i)
{
    float4 v = reinterpret_cast<const float4*>(in)[i];
    float vv[4] = {v.x, v.y, v.z, v.w};
    __nv_bfloat16 h[4], l[4];
#pragma unroll
    for (int k = 0; k < 4; k++) split2(vv[k], h[k], l[k]);
    __nv_bfloat162* hp = reinterpret_cast<__nv_bfloat162*>(hi) + 2 * i;
    __nv_bfloat162* lp = reinterpret_cast<__nv_bfloat162*>(lo) + 2 * i;
    __nv_bfloat162 t;
    t.x = h[0]; t.y = h[1]; hp[0] = t;
    t.x = h[2]; t.y = h[3]; hp[1] = t;
    t.x = l[0]; t.y = l[1]; lp[0] = t;
    t.x = l[2]; t.y = l[3]; lp[1] = t;
}

// Fused: residual copy + x -> bf16 hi/lo split (x read once)
__global__ void prep_x_kernel(const float* __restrict__ x,
                              float* __restrict__ resid,
                              __nv_bfloat16* __restrict__ hi,
                              __nv_bfloat16* __restrict__ lo, int n4)
{
    int i = blockIdx.x * 256 + threadIdx.x;
    if (i >= n4) return;
    float4 v = reinterpret_cast<const float4*>(x)[i];
    reinterpret_cast<float4*>(resid)[i] = v;
    float vv[4] = {v.x, v.y, v.z, v.w};
    __nv_bfloat16 h[4], l[4];
#pragma unroll
    for (int k = 0; k < 4; k++) split2(vv[k], h[k], l[k]);
    __nv_bfloat162* hp = reinterpret_cast<__nv_bfloat162*>(hi) + 2 * i;
    __nv_bfloat162* lp = reinterpret_cast<__nv_bfloat162*>(lo) + 2 * i;
    __nv_bfloat162 t;
    t.x = h[0]; t.y = h[1]; hp[0] = t;
    t.x = h[2]; t.y = h[3]; hp[1] = t;
    t.x = l[0]; t.y = l[1]; lp[0] = t;
    t.x = l[2]; t.y = l[3]; lp[1] = t;
}

// Fused per-direction weight splits (in_w | xproj_w | out_w), one launch.
__global__ void split_weights_kernel(const float* __restrict__ w1,
                                     __nv_bfloat16* __restrict__ w1h, __nv_bfloat16* __restrict__ w1l,
                                     const float* __restrict__ wx,
                                     __nv_bfloat16* __restrict__ wxh, __nv_bfloat16* __restrict__ wxl,
                                     const float* __restrict__ wo,
                                     __nv_bfloat16* __restrict__ woh, __nv_bfloat16* __restrict__ wol)
{
    const int N1 = E2 * DM / 4;
    const int N2 = 64 * DI / 4;
    const int N3 = DM * DI / 4;
    int i = blockIdx.x * 256 + threadIdx.x;
    if (i < N1) { split_body(w1, w1h, w1l, i); return; }
    i -= N1;
    if (i < N2) { split_body(wx, wxh, wxl, i); return; }
    i -= N2;
    if (i < N3) { split_body(wo, woh, wol, i); }
}

// ---------------- tensor-core NT GEMM, 3-term bf16 split, ldmatrix + 3-stage -------
// C[m,n] = sum_{k in [z*ksplit,(z+1)*ksplit)} A[m,k]*W[n,k]  (z = blockIdx.z)
// smem layout per stage/comp: [rows][32B of k]; 16B chunk swizzle phys = c ^ ((r>>2)&1)
template<int BM, int BN, int WM, int WN>
__global__ void __launch_bounds__((BM / WM) * (BN / WN) * 32)
mma_gemm_kernel(const __nv_bfloat16* __restrict__ Ahi, const __nv_bfloat16* __restrict__ Alo,
                const __nv_bfloat16* __restrict__ Bhi, const __nv_bfloat16* __restrict__ Blo,
                float* __restrict__ C, int ksplit,
                int lda, int acol0, int flip,
                int ldb, int ldc, int ccol0, long csplit_stride)
{
    constexpr int THREADS = (BM / WM) * (BN / WN) * 32;
    constexpr int WM16 = WM / 16;
    constexpr int WN8  = WN / 8;

    __shared__ __align__(16) uint8_t As[3 * 2 * BM * 32];   // [stage][comp][BM][32B]
    __shared__ __align__(16) uint8_t Bs[3 * 2 * BN * 32];

    const int tid  = threadIdx.x;
    const int bm0  = blockIdx.y * BM;
    const int bn0  = blockIdx.x * BN;
    const int kbeg = blockIdx.z * ksplit;
    const int KT   = ksplit / 16;
    C += (long)blockIdx.z * csplit_stride;

    const int wid  = tid >> 5;
    const int lane = tid & 31;
    const int wm   = wid / (BN / WN);
    const int wn   = wid % (BN / WN);
    const int g    = lane >> 2;
    const int t    = lane & 3;

    float acc[WM16][WN8][4];
#pragma unroll
    for (int i = 0; i < WM16; i++)
#pragma unroll
        for (int j = 0; j < WN8; j++)
#pragma unroll
            for (int q = 0; q < 4; q++) acc[i][j][q] = 0.f;

    auto loadA = [&](int st, int k0) {
        for (int i = tid; i < BM * 4; i += THREADS) {
            int comp = i / (BM * 2);
            int rem  = i - comp * BM * 2;
            int r = rem >> 1;
            int c = rem & 1;
            int mg = bm0 + r;
            int rowg = mg;
            if (flip) { int b = mg >> 11; int l = mg & 2047; rowg = (b << 11) + (2047 - l); }
            const __nv_bfloat16* src = (comp ? Alo : Ahi) + (long)rowg * lda + acol0 + k0 + c * 8;
            uint32_t dst = smem_u32(As + ((st * 2 + comp) * BM + r) * 32 + ((c ^ ((r >> 2) & 1)) << 4));
            CPASYNC16(dst, src);
        }
    };
    auto loadB = [&](int st, int k0) {
        for (int i = tid; i < BN * 4; i += THREADS) {
            int comp = i / (BN * 2);
            int rem  = i - comp * BN * 2;
            int r = rem >> 1;
            int c = rem & 1;
            const __nv_bfloat16* src = (comp ? Blo : Bhi) + (long)(bn0 + r) * ldb + k0 + c * 8;
            uint32_t dst = smem_u32(Bs + ((st * 2 + comp) * BN + r) * 32 + ((c ^ ((r >> 2) & 1)) << 4));
            CPASYNC16(dst, src);
        }
    };

    // ldmatrix address precompute (per-thread, stage-relative)
    // A x4: tile = lane>>3; row_off = (tile&1)*8 + (lane&7); chunk = tile>>1
    const int a_tile   = lane >> 3;
    const int a_rowoff = ((a_tile & 1) << 3) + (lane & 7);
    const int a_chunk  = a_tile >> 1;
    // B x4 (covers j, j+1): tile = lane>>3; row_off = ((tile>>1)<<3) + (lane&7); chunk = tile&1
    const int b_rowoff = (((lane >> 4) & 1) << 3) + (lane & 7);
    const int b_chunk  = (lane >> 3) & 1;

    // prologue: stages 0 and 1
    loadA(0, kbeg); loadB(0, kbeg); CPCOMMIT();
    if (KT > 1) { loadA(1, kbeg + 16); loadB(1, kbeg + 16); }
    CPCOMMIT();

    for (int kt = 0; kt < KT; kt++) {
        CPWAIT1();
        __syncthreads();

        // issue stage kt+2 (safe: sync above guarantees all warps done reading it)
        if (kt + 2 < KT) { loadA((kt + 2) % 3, kbeg + (kt + 2) * 16); loadB((kt + 2) % 3, kbeg + (kt + 2) * 16); }
        CPCOMMIT();

        const int st = kt % 3;
        const uint8_t* Ah = As + (st * 2 + 0) * BM * 32;
        const uint8_t* Al = As + (st * 2 + 1) * BM * 32;
        const uint8_t* Bh = Bs + (st * 2 + 0) * BN * 32;
        const uint8_t* Bl = Bs + (st * 2 + 1) * BN * 32;

        uint32_t ah[WM16][4], al[WM16][4], bh[WN8][2], bl[WN8][2];
#pragma unroll
        for (int i = 0; i < WM16; i++) {
            int r = wm * WM + i * 16 + a_rowoff;
            uint32_t off = r * 32 + (((a_chunk ^ ((r >> 2) & 1))) << 4);
            ldsm_x4(ah[i][0], ah[i][1], ah[i][2], ah[i][3], smem_u32(Ah + off));
            ldsm_x4(al[i][0], al[i][1], al[i][2], al[i][3], smem_u32(Al + off));
        }
#pragma unroll
        for (int jp = 0; jp < WN8 / 2; jp++) {
            int r = wn * WN + jp * 16 + b_rowoff;
            uint32_t off = r * 32 + (((b_chunk ^ ((r >> 2) & 1))) << 4);
            ldsm_x4(bh[2 * jp][0], bh[2 * jp][1], bh[2 * jp + 1][0], bh[2 * jp + 1][1], smem_u32(Bh + off));
            ldsm_x4(bl[2 * jp][0], bl[2 * jp][1], bl[2 * jp + 1][0], bl[2 * jp + 1][1], smem_u32(Bl + off));
        }
#pragma unroll
        for (int i = 0; i < WM16; i++)
#pragma unroll
            for (int j = 0; j < WN8; j++) {
                mma_bf16(acc[i][j], ah[i], bh[j]);
                mma_bf16(acc[i][j], ah[i], bl[j]);
                mma_bf16(acc[i][j], al[i], bh[j]);
            }
    }

    // epilogue: fp32 direct store (cols 2t,2t+1 contiguous -> float2)
#pragma unroll
    for (int i = 0; i < WM16; i++) {
#pragma unroll
        for (int j = 0; j < WN8; j++) {
            int r  = bm0 + wm * WM + i * 16 + g;
            int n0 = bn0 + ccol0 + wn * WN + j * 8 + 2 * t;
            float2 v0 = make_float2(acc[i][j][0], acc[i][j][1]);
            float2 v1 = make_float2(acc[i][j][2], acc[i][j][3]);
            *reinterpret_cast<float2*>(&C[(long)r * ldc + n0])       = v0;
            *reinterpret_cast<float2*>(&C[(long)(r + 8) * ldc + n0]) = v1;
        }
    }
}

// ---------------- split-K reduction: dbc = sum_z part[z] ---------------------------
__global__ void reduce_partials_kernel(const float* __restrict__ part, float* __restrict__ dbc, int n4)
{
    int i = blockIdx.x * 256 + threadIdx.x;
    if (i >= n4) return;
    float4 a = reinterpret_cast<const float4*>(part)[i];
#pragma unroll
    for (int z = 1; z < KSPLIT; z++) {
        float4 b = reinterpret_cast<const float4*>(part + (long)z * MROWS * 64)[i];
        a.x += b.x; a.y += b.y; a.z += b.z; a.w += b.w;
    }
    reinterpret_cast<float4*>(dbc)[i] = a;
}

// ---------------- depthwise causal conv(4) + silu (+ bf16 split out) ---------------
__global__ void conv_silu_kernel(const float* __restrict__ xz,
                                 const float* __restrict__ cw,
                                 const float* __restrict__ cb,
                                 float* __restrict__ xc,
                                 __nv_bfloat16* __restrict__ xch,
                                 __nv_bfloat16* __restrict__ xcl)
{
    int c  = blockIdx.x * blockDim.x + threadIdx.x;   // channel in [0,DI)
    int l0 = blockIdx.y * 8;
    int b  = blockIdx.z;

    float w0 = cw[c * 4 + 0], w1 = cw[c * 4 + 1], w2 = cw[c * 4 + 2], w3 = cw[c * 4 + 3];
    float bias = cb[c];

    float v[11];
#pragma unroll
    for (int j = 0; j < 11; j++) {
        int l = l0 - 3 + j;
        v[j] = (l >= 0) ? xz[(long)(b * LL + l) * E2 + c] : 0.f;
    }
#pragma unroll
    for (int i = 0; i < 8; i++) {
        float a = v[i] * w0 + v[i + 1] * w1 + v[i + 2] * w2 + v[i + 3] * w3 + bias;
        float s = a / (1.f + __expf(-a));   // silu
        long idx = (long)(b * LL + l0 + i) * DI + c;
        xc[idx] = s;
        __nv_bfloat16 h, l2;
        split2(s, h, l2);
        xch[idx] = h;
        xcl[idx] = l2;
    }
}

// ---------------- delta = softplus(dt @ dt_w^T + dt_b) ---------------------------
__global__ void delta_kernel(const float* __restrict__ dbc,
                             const float* __restrict__ dt_w,
                             const float* __restrict__ dt_b,
                             float* __restrict__ delta)
{
    int d  = blockIdx.x * 256 + threadIdx.x;  // [0,DI)
    int m0 = blockIdx.y * 4;

    float w[DTR];
    const float4* w4 = reinterpret_cast<const float4*>(dt_w + (long)d * DTR);
#pragma unroll
    for (int r = 0; r < DTR / 4; r++) {
        float4 v = w4[r];
        w[4 * r + 0] = v.x; w[4 * r + 1] = v.y; w[4 * r + 2] = v.z; w[4 * r + 3] = v.w;
    }
    float bias = dt_b[d];

#pragma unroll
    for (int mi = 0; mi < 4; mi++) {
        const float* row = dbc + (long)(m0 + mi) * 64;
        float acc = bias;
#pragma unroll
        for (int r = 0; r < DTR; r++) acc = fmaf(row[r], w[r], acc);
        float sp = (acc > 20.f) ? acc : log1pf(__expf(acc));
        delta[(long)(m0 + mi) * DI + d] = sp;
    }
}

// ---------------- scan pass1: chunk-local scan from h=0, record summary -----------
__global__ void scan_pass1_kernel(const float* __restrict__ delta,
                                  const float* __restrict__ xc,
                                  const float* __restrict__ dbc,
                                  const float* __restrict__ A_log,
                                  float* __restrict__ cs,
                                  float* __restrict__ he)
{
    __shared__ float sB[LC][DS];
    int chunk = blockIdx.x;
    int d     = blockIdx.y * 256 + threadIdx.x;
    int b     = blockIdx.z;
    int m0    = b * LL + chunk * LC;

    const float* dbc0 = dbc + (long)m0 * 64;
    for (int i = threadIdx.x; i < LC * DS; i += 256) {
        int tt = i >> 4, s = i & 15;
        sB[tt][s] = dbc0[tt * 64 + 32 + s];
    }
    __syncthreads();

    float Aa[DS];
#pragma unroll
    for (int s = 0; s < DS; s++) Aa[s] = -__expf(A_log[d * DS + s]);
    float a0 = Aa[0];
    bool fast = true;
#pragma unroll
    for (int s = 1; s < DS; s++) fast = fast && (fabsf(Aa[s] - (s + 1) * a0) < 1e-4f * fabsf(Aa[s]));

    float h[DS];
#pragma unroll
    for (int s = 0; s < DS; s++) h[s] = 0.f;
    float S = 0.f;

    if (fast) {
        for (int tt = 0; tt < LC; tt++) {
            int m = m0 + tt;
            float dlt = delta[(long)m * DI + d];
            float xcv = xc[(long)m * DI + d];
            S += dlt;
            float du = dlt * xcv;
            float e1 = __expf(dlt * a0);
            float p = e1;
#pragma unroll
            for (int s = 0; s < DS; s++) {
                h[s] = fmaf(h[s], p, du * sB[tt][s]);
                p *= e1;
            }
        }
    } else {
        for (int tt = 0; tt < LC; tt++) {
            int m = m0 + tt;
            float dlt = delta[(long)m * DI + d];
            float xcv = xc[(long)m * DI + d];
            S += dlt;
            float du = dlt * xcv;
#pragma unroll
            for (int s = 0; s < DS; s++) {
                float da = __expf(dlt * Aa[s]);
                h[s] = fmaf(h[s], da, du * sB[tt][s]);
            }
        }
    }

    cs[(long)(b * NC + chunk) * DI + d] = S;
    float* hout = he + ((long)(b * NC + chunk) * DI + d) * DS;
#pragma unroll
    for (int s = 0; s < DS; s++) hout[s] = h[s];
}

// ---------------- scan fixup: sequential over the 16 chunks -----------------------
__global__ void scan_fixup_kernel(const float* __restrict__ cs,
                                  const float* __restrict__ he,
                                  const float* __restrict__ A_log,
                                  float* __restrict__ hs)
{
    int idx = blockIdx.x * 256 + threadIdx.x;      // BB*DI*DS threads
    int s = idx & 15;
    int d = (idx >> 4) & (DI - 1);
    int b = idx >> 14;

    float A = -__expf(A_log[d * DS + s]);
    float h = 0.f;
    for (int c = 0; c < NC; c++) {
        long base = ((long)(b * NC + c) * DI + d) * DS + s;
        hs[base] = h;
        float S = cs[(long)(b * NC + c) * DI + d];
        h = __expf(A * S) * h + he[base];
    }
}

// ---------------- scan pass3: replay with h_start, emit gated y (bf16 hi/lo) ------
__global__ void scan_pass3_kernel(const float* __restrict__ delta,
                                  const float* __restrict__ xc,
                                  const float* __restrict__ dbc,
                                  const float* __restrict__ A_log,
                                  const float* __restrict__ hs,
                                  const float* __restrict__ Dp,
                                  const float* __restrict__ xz,
                                  __nv_bfloat16* __restrict__ ymh,
                                  __nv_bfloat16* __restrict__ yml)
{
    __shared__ float sB[LC][DS];
    __shared__ float sC[LC][DS];
    int chunk = blockIdx.x;
    int d     = blockIdx.y * 256 + threadIdx.x;
    int b     = blockIdx.z;
    int m0    = b * LL + chunk * LC;

    const float* dbc0 = dbc + (long)m0 * 64;
    for (int i = threadIdx.x; i < LC * DS; i += 256) {
        int tt = i >> 4, s = i & 15;
        sB[tt][s] = dbc0[tt * 64 + 32 + s];
        sC[tt][s] = dbc0[tt * 64 + 48 + s];
    }
    __syncthreads();

    float Aa[DS];
#pragma unroll
    for (int s = 0; s < DS; s++) Aa[s] = -__expf(A_log[d * DS + s]);
    float a0 = Aa[0];
    bool fast = true;
#pragma unroll
    for (int s = 1; s < DS; s++) fast = fast && (fabsf(Aa[s] - (s + 1) * a0) < 1e-4f * fabsf(Aa[s]));

    float h[DS];
    const float* hin = hs + ((long)(b * NC + chunk) * DI + d) * DS;
#pragma unroll
    for (int s = 0; s < DS; s++) h[s] = hin[s];

    float Dv = Dp[d];

    for (int tt = 0; tt < LC; tt++) {
        int m = m0 + tt;
        float dlt = delta[(long)m * DI + d];
        float xcv = xc[(long)m * DI + d];
        float du = dlt * xcv;
        float y = 0.f;
        if (fast) {
            float e1 = __expf(dlt * a0);
            float p = e1;
#pragma unroll
            for (int s = 0; s < DS; s++) {
                h[s] = fmaf(h[s], p, du * sB[tt][s]);
                y = fmaf(h[s], sC[tt][s], y);
                p *= e1;
            }
        } else {
#pragma unroll
            for (int s = 0; s < DS; s++) {
                float da = __expf(dlt * Aa[s]);
                h[s] = fmaf(h[s], da, du * sB[tt][s]);
                y = fmaf(h[s], sC[tt][s], y);
            }
        }
        float z = xz[(long)m * E2 + DI + d];
        float sil = z / (1.f + __expf(-z));
        float out = (y + xcv * Dv) * sil;
        __nv_bfloat16 hh, ll;
        split2(out, hh, ll);
        long idx = (long)m * DI + d;
        ymh[idx] = hh;
        yml[idx] = ll;
    }
}

// ---------------- host launcher ---------------------------------------------------
extern "C" void kernel_launch(void* const* d_in, const int* in_sizes, int n_in,
                              void* d_out, int out_size)
{
    const float* x = (const float*)d_in[0];
    float* out = (float*)d_out;

    float *xz_base, *xc_base, *dbc_base, *part_base, *delta_base, *cs_base, *he_base, *hs_base;
    cudaGetSymbolAddress((void**)&xz_base,    g_xz);
    cudaGetSymbolAddress((void**)&xc_base,    g_xc);
    cudaGetSymbolAddress((void**)&dbc_base,   g_dbc);
    cudaGetSymbolAddress((void**)&part_base,  g_part);
    cudaGetSymbolAddress((void**)&delta_base, g_delta);
    cudaGetSymbolAddress((void**)&cs_base,    g_cs);
    cudaGetSymbolAddress((void**)&he_base,    g_he);
    cudaGetSymbolAddress((void**)&hs_base,    g_hs);

    __nv_bfloat16 *xbh, *xbl, *w1h, *w1l, *wxh, *wxl, *woh, *wol, *xch, *xcl, *ymh, *yml;
    cudaGetSymbolAddress((void**)&xbh, g_xbh);
    cudaGetSymbolAddress((void**)&xbl, g_xbl);
    cudaGetSymbolAddress((void**)&w1h, g_w1h);
    cudaGetSymbolAddress((void**)&w1l, g_w1l);
    cudaGetSymbolAddress((void**)&wxh, g_wxh);
    cudaGetSymbolAddress((void**)&wxl, g_wxl);
    cudaGetSymbolAddress((void**)&woh, g_woh);
    cudaGetSymbolAddress((void**)&wol, g_wol);
    cudaGetSymbolAddress((void**)&xch, g_xch);
    cudaGetSymbolAddress((void**)&xcl, g_xcl);
    cudaGetSymbolAddress((void**)&ymh, g_ymh);
    cudaGetSymbolAddress((void**)&yml, g_yml);

    const long HID = (long)MROWS * DIM;

    // fused residual copy + x bf16 split
    prep_x_kernel<<<(MROWS * DIM / 4 + 255) / 256, 256>>>(x, out + HID, xbh, xbl, MROWS * DIM / 4);

    const int NW = (E2 * DM / 4) + (64 * DI / 4) + (DM * DI / 4);

    for (int dir = 0; dir < 2; dir++) {
        const float* in_w    = (const float*)d_in[1 + dir * 9 + 0];
        const float* conv_w  = (const float*)d_in[1 + dir * 9 + 1];
        const float* conv_b  = (const float*)d_in[1 + dir * 9 + 2];
        const float* xproj_w = (const float*)d_in[1 + dir * 9 + 3];
        const float* dt_w    = (const float*)d_in[1 + dir * 9 + 4];
        const float* dt_b    = (const float*)d_in[1 + dir * 9 + 5];
        const float* A_log   = (const float*)d_in[1 + dir * 9 + 6];
        const float* Dp      = (const float*)d_in[1 + dir * 9 + 7];
        const float* out_w   = (const float*)d_in[1 + dir * 9 + 8];

        float* xz    = xz_base    + (long)dir * MROWS * E2;
        float* xc    = xc_base    + (long)dir * MROWS * DI;
        float* dbc   = dbc_base   + (long)dir * MROWS * 64;
        float* delta = delta_base + (long)dir * MROWS * DI;
        float* cs    = cs_base    + (long)dir * BB * NC * DI;
        float* he    = he_base    + (long)dir * BB * NC * DI * DS;
        float* hs    = hs_base    + (long)dir * BB * NC * DI * DS;

        __nv_bfloat16* w1h_d = w1h + (long)dir * E2 * DM;
        __nv_bfloat16* w1l_d = w1l + (long)dir * E2 * DM;
        __nv_bfloat16* wxh_d = wxh + (long)dir * 64 * DI;
        __nv_bfloat16* wxl_d = wxl + (long)dir * 64 * DI;
        __nv_bfloat16* woh_d = woh + (long)dir * DM * DI;
        __nv_bfloat16* wol_d = wol + (long)dir * DM * DI;
        __nv_bfloat16* xch_d = xch + (long)dir * MROWS * DI;
        __nv_bfloat16* xcl_d = xcl + (long)dir * MROWS * DI;
        __nv_bfloat16* ymh_d = ymh + (long)dir * MROWS * DI;
        __nv_bfloat16* yml_d = yml + (long)dir * MROWS * DI;

        // fused weight splits (one launch per direction)
        split_weights_kernel<<<(NW + 255) / 256, 256>>>(
            in_w, w1h_d, w1l_d, xproj_w, wxh_d, wxl_d, out_w, woh_d, wol_d);

        // 1) xz = x_dir @ in_w^T    (M=4096, N=2048, K=512)
        mma_gemm_kernel<128, 128, 64, 32><<<dim3(E2 / 128, MROWS / 128, 1), 256>>>(
            xbh, xbl, w1h_d, w1l_d, xz, DM,
            /*lda*/ DIM, /*acol0*/ dir * DM, /*flip*/ dir,
            /*ldb*/ DM, /*ldc*/ E2, /*ccol0*/ 0, 0);

        // 2) xc = silu(causal depthwise conv4(xh) + b), emits fp32 + bf16 hi/lo
        conv_silu_kernel<<<dim3(DI / 256, LL / 8, BB), 256>>>(xz, conv_w, conv_b, xc, xch_d, xcl_d);

        // 3) dbc = xc @ xproj_w^T   (M=4096, N=64, K=1024), split-K=4 + reduce
        mma_gemm_kernel<64, 64, 32, 32><<<dim3(1, MROWS / 64, KSPLIT), 128>>>(
            xch_d, xcl_d, wxh_d, wxl_d, part_base, DI / KSPLIT,
            DI, 0, 0, DI, 64, 0, (long)MROWS * 64);
        reduce_partials_kernel<<<(MROWS * 64 / 4 + 255) / 256, 256>>>(part_base, dbc, MROWS * 64 / 4);

        // 4) delta = softplus(dt @ dt_w^T + dt_b)
        delta_kernel<<<dim3(DI / 256, MROWS / 4), 256>>>(dbc, dt_w, dt_b, delta);

        // 5-7) chunked parallel scan
        scan_pass1_kernel<<<dim3(NC, DI / 256, BB), 256>>>(delta, xc, dbc, A_log, cs, he);
        scan_fixup_kernel<<<(BB * DI * DS) / 256, 256>>>(cs, he, A_log, hs);
        scan_pass3_kernel<<<dim3(NC, DI / 256, BB), 256>>>(delta, xc, dbc, A_log, hs, Dp, xz, ymh_d, yml_d);

        // 8) hidden[:, :, dir*512 : dir*512+512] = ym @ out_w^T  (M=4096, N=512, K=1024)
        mma_gemm_kernel<128, 128, 64, 32><<<dim3(DM / 128, MROWS / 128, 1), 256>>>(
            ymh_d, yml_d, woh_d, wol_d, out, DI,
            DI, 0, 0, DI, DIM, dir * DM, 0);
    }
}

// round 5
// speedup vs baseline: 2.7213x; 1.2571x over previous
#include <cuda_runtime.h>
#include <cuda_bf16.h>
#include <cstdint>

// Problem constants
#define BB    2
#define LL    2048
#define DIM   1024
#define DM    512
#define DI    1024
#define E2    2048      // 2*DI
#define MROWS 4096      // BB*LL
#define DS    16        // D_STATE
#define DTR   32        // DT_RANK
#define NC    16        // scan chunks
#define LC    128       // chunk length (NC*LC == LL)
#define KSPLIT 4        // split-K factor for xproj GEMM

// ---------------- scratch (static device memory; no allocation allowed) ----------
__device__ float g_xz   [2][MROWS * E2];       // in-proj output (xh | z)
__device__ float g_xc   [2][MROWS * DI];       // conv+silu output (fp32 for scan)
__device__ float g_dbc  [2][MROWS * 64];       // x-proj output (dt|B|C)
__device__ float g_part [2][KSPLIT][MROWS * 64]; // split-K partials for xproj
__device__ float g_delta[2][MROWS * DI];       // softplus(dt @ dt_w^T + dt_b)
__device__ float g_cs   [2][BB * NC * DI];            // per-chunk sum of delta
__device__ float g_he   [2][BB * NC * DI * DS];       // chunk-local h_end
__device__ float g_hs   [2][BB * NC * DI * DS];       // chunk h_start (after fixup)

// bf16 hi/lo split operands for tensor-core GEMMs
__device__ __nv_bfloat16 g_xbh [MROWS * DIM];
__device__ __nv_bfloat16 g_xbl [MROWS * DIM];
__device__ __nv_bfloat16 g_w1h [2][E2 * DM];
__device__ __nv_bfloat16 g_w1l [2][E2 * DM];
__device__ __nv_bfloat16 g_wxh [2][64 * DI];
__device__ __nv_bfloat16 g_wxl [2][64 * DI];
__device__ __nv_bfloat16 g_woh [2][DM * DI];
__device__ __nv_bfloat16 g_wol [2][DM * DI];
__device__ __nv_bfloat16 g_xch [2][MROWS * DI];
__device__ __nv_bfloat16 g_xcl [2][MROWS * DI];
__device__ __nv_bfloat16 g_ymh [2][MROWS * DI];
__device__ __nv_bfloat16 g_yml [2][MROWS * DI];

// ---------------- helpers ----------------------------------------------------------
__device__ __forceinline__ void split2(float v, __nv_bfloat16& h, __nv_bfloat16& l) {
    h = __float2bfloat16(v);
    l = __float2bfloat16(v - __bfloat162float(h));
}

__device__ __forceinline__ void mma_bf16(float* c, const uint32_t* a, const uint32_t* b) {
    asm volatile(
        "mma.sync.aligned.m16n8k16.row.col.f32.bf16.bf16.f32 "
        "{%0,%1,%2,%3}, {%4,%5,%6,%7}, {%8,%9}, {%0,%1,%2,%3};\n"
        : "+f"(c[0]), "+f"(c[1]), "+f"(c[2]), "+f"(c[3])
        : "r"(a[0]), "r"(a[1]), "r"(a[2]), "r"(a[3]), "r"(b[0]), "r"(b[1]));
}

__device__ __forceinline__ void ldsm_x4(uint32_t& r0, uint32_t& r1, uint32_t& r2, uint32_t& r3, uint32_t a) {
    asm volatile("ldmatrix.sync.aligned.m8n8.x4.shared.b16 {%0,%1,%2,%3}, [%4];"
                 : "=r"(r0), "=r"(r1), "=r"(r2), "=r"(r3) : "r"(a));
}

#define CPASYNC16(dst, src) asm volatile("cp.async.cg.shared.global [%0], [%1], 16;\n" :: "r"(dst), "l"(src))
#define CPCOMMIT()          asm volatile("cp.async.commit_group;\n")
#define CPWAIT1()           asm volatile("cp.async.wait_group 1;\n")

__device__ __forceinline__ uint32_t smem_u32(const void* p) {
    return (uint32_t)__cvta_generic_to_shared(p);
}

// ---------------- split fp32 -> bf16 hi/lo (vectorized float4) ---------------------
__device__ __forceinline__ void split_body(const float* __restrict__ in,
                                           __nv_bfloat16* __restrict__ hi,
                                           __nv_bfloat16* __restrict__ lo, int i)
{
    float4 v = reinterpret_cast<const float4*>(in)[i];
    float vv[4] = {v.x, v.y, v.z, v.w};
    __nv_bfloat16 h[4], l[4];
#pragma unroll
    for (int k = 0; k < 4; k++) split2(vv[k], h[k], l[k]);
    __nv_bfloat162* hp = reinterpret_cast<__nv_bfloat162*>(hi) + 2 * i;
    __nv_bfloat162* lp = reinterpret_cast<__nv_bfloat162*>(lo) + 2 * i;
    __nv_bfloat162 t;
    t.x = h[0]; t.y = h[1]; hp[0] = t;
    t.x = h[2]; t.y = h[3]; hp[1] = t;
    t.x = l[0]; t.y = l[1]; lp[0] = t;
    t.x = l[2]; t.y = l[3]; lp[1] = t;
}

// Fused: residual copy + x -> bf16 hi/lo split (x read once)
__global__ void prep_x_kernel(const float* __restrict__ x,
                              float* __restrict__ resid,
                              __nv_bfloat16* __restrict__ hi,
                              __nv_bfloat16* __restrict__ lo, int n4)
{
    int i = blockIdx.x * 256 + threadIdx.x;
    if (i >= n4) return;
    float4 v = reinterpret_cast<const float4*>(x)[i];
    reinterpret_cast<float4*>(resid)[i] = v;
    float vv[4] = {v.x, v.y, v.z, v.w};
    __nv_bfloat16 h[4], l[4];
#pragma unroll
    for (int k = 0; k < 4; k++) split2(vv[k], h[k], l[k]);
    __nv_bfloat162* hp = reinterpret_cast<__nv_bfloat162*>(hi) + 2 * i;
    __nv_bfloat162* lp = reinterpret_cast<__nv_bfloat162*>(lo) + 2 * i;
    __nv_bfloat162 t;
    t.x = h[0]; t.y = h[1]; hp[0] = t;
    t.x = h[2]; t.y = h[3]; hp[1] = t;
    t.x = l[0]; t.y = l[1]; lp[0] = t;
    t.x = l[2]; t.y = l[3]; lp[1] = t;
}

// Batched per-direction weight splits (in_w | xproj_w | out_w), both dirs, one launch.
__global__ void split_weights_kernel(const float* __restrict__ w1a, const float* __restrict__ w1b,
                                     const float* __restrict__ wxa, const float* __restrict__ wxb,
                                     const float* __restrict__ woa, const float* __restrict__ wob,
                                     __nv_bfloat16* __restrict__ w1h, __nv_bfloat16* __restrict__ w1l,
                                     __nv_bfloat16* __restrict__ wxh, __nv_bfloat16* __restrict__ wxl,
                                     __nv_bfloat16* __restrict__ woh, __nv_bfloat16* __restrict__ wol)
{
    const int N1 = E2 * DM / 4;
    const int N2 = 64 * DI / 4;
    const int N3 = DM * DI / 4;
    int dir = blockIdx.y;
    const float* w1 = dir ? w1b : w1a;
    const float* wx = dir ? wxb : wxa;
    const float* wo = dir ? wob : woa;
    int i = blockIdx.x * 256 + threadIdx.x;
    if (i < N1) { split_body(w1, w1h + (long)dir * E2 * DM, w1l + (long)dir * E2 * DM, i); return; }
    i -= N1;
    if (i < N2) { split_body(wx, wxh + (long)dir * 64 * DI, wxl + (long)dir * 64 * DI, i); return; }
    i -= N2;
    if (i < N3) { split_body(wo, woh + (long)dir * DM * DI, wol + (long)dir * DM * DI, i); }
}

// ---------------- tensor-core NT GEMM, 3-term bf16 split, ldmatrix + 3-stage -------
// Batched over blockIdx.z = dir*nks + kz.
// C[m,n] += sum_{k in [kz*ksplit,(kz+1)*ksplit)} A_dir[m,k]*W_dir[n,k]
template<int BM, int BN, int WM, int WN>
__global__ void __launch_bounds__((BM / WM) * (BN / WN) * 32)
mma_gemm_kernel(const __nv_bfloat16* __restrict__ Ahi, const __nv_bfloat16* __restrict__ Alo,
                const __nv_bfloat16* __restrict__ Bhi, const __nv_bfloat16* __restrict__ Blo,
                float* __restrict__ C, int ksplit, int nks,
                int lda, long a_dstride, int acol0_step, int flip_is_dir,
                int ldb, long b_dstride,
                int ldc, long c_dstride, int ccol0_step, long csplit_stride)
{
    constexpr int THREADS = (BM / WM) * (BN / WN) * 32;
    constexpr int WM16 = WM / 16;
    constexpr int WN8  = WN / 8;

    __shared__ __align__(16) uint8_t As[3 * 2 * BM * 32];   // [stage][comp][BM][32B]
    __shared__ __align__(16) uint8_t Bs[3 * 2 * BN * 32];

    const int tid  = threadIdx.x;
    const int bm0  = blockIdx.y * BM;
    const int bn0  = blockIdx.x * BN;
    const int z    = blockIdx.z;
    const int dir  = z / nks;
    const int kz   = z - dir * nks;
    const int kbeg = kz * ksplit;
    const int KT   = ksplit / 16;

    const __nv_bfloat16* Ahp = Ahi + (long)dir * a_dstride;
    const __nv_bfloat16* Alp = Alo + (long)dir * a_dstride;
    const __nv_bfloat16* Bhp = Bhi + (long)dir * b_dstride;
    const __nv_bfloat16* Blp = Blo + (long)dir * b_dstride;
    const int acol0 = dir * acol0_step;
    const int ccol0 = dir * ccol0_step;
    const int flip  = flip_is_dir ? dir : 0;
    C += (long)dir * c_dstride + (long)kz * csplit_stride;

    const int wid  = tid >> 5;
    const int lane = tid & 31;
    const int wm   = wid / (BN / WN);
    const int wn   = wid % (BN / WN);
    const int g    = lane >> 2;
    const int t    = lane & 3;

    float acc[WM16][WN8][4];
#pragma unroll
    for (int i = 0; i < WM16; i++)
#pragma unroll
        for (int j = 0; j < WN8; j++)
#pragma unroll
            for (int q = 0; q < 4; q++) acc[i][j][q] = 0.f;

    auto loadA = [&](int st, int k0) {
        for (int i = tid; i < BM * 4; i += THREADS) {
            int comp = i / (BM * 2);
            int rem  = i - comp * BM * 2;
            int r = rem >> 1;
            int c = rem & 1;
            int mg = bm0 + r;
            int rowg = mg;
            if (flip) { int b = mg >> 11; int l = mg & 2047; rowg = (b << 11) + (2047 - l); }
            const __nv_bfloat16* src = (comp ? Alp : Ahp) + (long)rowg * lda + acol0 + k0 + c * 8;
            uint32_t dst = smem_u32(As + ((st * 2 + comp) * BM + r) * 32 + ((c ^ ((r >> 2) & 1)) << 4));
            CPASYNC16(dst, src);
        }
    };
    auto loadB = [&](int st, int k0) {
        for (int i = tid; i < BN * 4; i += THREADS) {
            int comp = i / (BN * 2);
            int rem  = i - comp * BN * 2;
            int r = rem >> 1;
            int c = rem & 1;
            const __nv_bfloat16* src = (comp ? Blp : Bhp) + (long)(bn0 + r) * ldb + k0 + c * 8;
            uint32_t dst = smem_u32(Bs + ((st * 2 + comp) * BN + r) * 32 + ((c ^ ((r >> 2) & 1)) << 4));
            CPASYNC16(dst, src);
        }
    };

    const int a_tile   = lane >> 3;
    const int a_rowoff = ((a_tile & 1) << 3) + (lane & 7);
    const int a_chunk  = a_tile >> 1;
    const int b_rowoff = (((lane >> 4) & 1) << 3) + (lane & 7);
    const int b_chunk  = (lane >> 3) & 1;

    // prologue: stages 0 and 1
    loadA(0, kbeg); loadB(0, kbeg); CPCOMMIT();
    if (KT > 1) { loadA(1, kbeg + 16); loadB(1, kbeg + 16); }
    CPCOMMIT();

    for (int kt = 0; kt < KT; kt++) {
        CPWAIT1();
        __syncthreads();

        if (kt + 2 < KT) { loadA((kt + 2) % 3, kbeg + (kt + 2) * 16); loadB((kt + 2) % 3, kbeg + (kt + 2) * 16); }
        CPCOMMIT();

        const int st = kt % 3;
        const uint8_t* Ah = As + (st * 2 + 0) * BM * 32;
        const uint8_t* Al = As + (st * 2 + 1) * BM * 32;
        const uint8_t* Bh = Bs + (st * 2 + 0) * BN * 32;
        const uint8_t* Bl = Bs + (st * 2 + 1) * BN * 32;

        uint32_t ah[WM16][4], al[WM16][4], bh[WN8][2], bl[WN8][2];
#pragma unroll
        for (int i = 0; i < WM16; i++) {
            int r = wm * WM + i * 16 + a_rowoff;
            uint32_t off = r * 32 + (((a_chunk ^ ((r >> 2) & 1))) << 4);
            ldsm_x4(ah[i][0], ah[i][1], ah[i][2], ah[i][3], smem_u32(Ah + off));
            ldsm_x4(al[i][0], al[i][1], al[i][2], al[i][3], smem_u32(Al + off));
        }
#pragma unroll
        for (int jp = 0; jp < WN8 / 2; jp++) {
            int r = wn * WN + jp * 16 + b_rowoff;
            uint32_t off = r * 32 + (((b_chunk ^ ((r >> 2) & 1))) << 4);
            ldsm_x4(bh[2 * jp][0], bh[2 * jp][1], bh[2 * jp + 1][0], bh[2 * jp + 1][1], smem_u32(Bh + off));
            ldsm_x4(bl[2 * jp][0], bl[2 * jp][1], bl[2 * jp + 1][0], bl[2 * jp + 1][1], smem_u32(Bl + off));
        }
#pragma unroll
        for (int i = 0; i < WM16; i++)
#pragma unroll
            for (int j = 0; j < WN8; j++) {
                mma_bf16(acc[i][j], ah[i], bh[j]);
                mma_bf16(acc[i][j], ah[i], bl[j]);
                mma_bf16(acc[i][j], al[i], bh[j]);
            }
    }

    // epilogue: fp32 direct store (cols 2t,2t+1 contiguous -> float2)
#pragma unroll
    for (int i = 0; i < WM16; i++) {
#pragma unroll
        for (int j = 0; j < WN8; j++) {
            int r  = bm0 + wm * WM + i * 16 + g;
            int n0 = bn0 + ccol0 + wn * WN + j * 8 + 2 * t;
            float2 v0 = make_float2(acc[i][j][0], acc[i][j][1]);
            float2 v1 = make_float2(acc[i][j][2], acc[i][j][3]);
            *reinterpret_cast<float2*>(&C[(long)r * ldc + n0])       = v0;
            *reinterpret_cast<float2*>(&C[(long)(r + 8) * ldc + n0]) = v1;
        }
    }
}

// ---------------- split-K reduction: dbc[dir] = sum_z part[dir][z], both dirs ------
__global__ void reduce_partials_kernel(const float* __restrict__ part, float* __restrict__ dbc)
{
    const int n4 = MROWS * 64 / 4;             // per-dir float4 count
    int i = blockIdx.x * 256 + threadIdx.x;    // over 2*n4
    if (i >= 2 * n4) return;
    int dir = i / n4;
    int j = i - dir * n4;
    const float* p = part + (long)dir * KSPLIT * MROWS * 64;
    float4 a = reinterpret_cast<const float4*>(p)[j];
#pragma unroll
    for (int z = 1; z < KSPLIT; z++) {
        float4 b = reinterpret_cast<const float4*>(p + (long)z * MROWS * 64)[j];
        a.x += b.x; a.y += b.y; a.z += b.z; a.w += b.w;
    }
    reinterpret_cast<float4*>(dbc + (long)dir * MROWS * 64)[j] = a;
}

// ---------------- depthwise causal conv(4) + silu (+ bf16 split out), batched ------
__global__ void conv_silu_kernel(const float* __restrict__ xz_base,
                                 const float* __restrict__ cwa, const float* __restrict__ cwb,
                                 const float* __restrict__ cba, const float* __restrict__ cbb,
                                 float* __restrict__ xc_base,
                                 __nv_bfloat16* __restrict__ xch_base,
                                 __nv_bfloat16* __restrict__ xcl_base)
{
    int c  = blockIdx.x * blockDim.x + threadIdx.x;   // channel in [0,DI)
    int l0 = blockIdx.y * 8;
    int zb = blockIdx.z;
    int dir = zb >> 1;
    int b   = zb & 1;

    const float* cw = dir ? cwb : cwa;
    const float* cb = dir ? cbb : cba;
    const float* xz = xz_base + (long)dir * MROWS * E2;
    float* xc = xc_base + (long)dir * MROWS * DI;
    __nv_bfloat16* xch = xch_base + (long)dir * MROWS * DI;
    __nv_bfloat16* xcl = xcl_base + (long)dir * MROWS * DI;

    float w0 = cw[c * 4 + 0], w1 = cw[c * 4 + 1], w2 = cw[c * 4 + 2], w3 = cw[c * 4 + 3];
    float bias = cb[c];

    float v[11];
#pragma unroll
    for (int j = 0; j < 11; j++) {
        int l = l0 - 3 + j;
        v[j] = (l >= 0) ? xz[(long)(b * LL + l) * E2 + c] : 0.f;
    }
#pragma unroll
    for (int i = 0; i < 8; i++) {
        float a = v[i] * w0 + v[i + 1] * w1 + v[i + 2] * w2 + v[i + 3] * w3 + bias;
        float s = a / (1.f + __expf(-a));   // silu
        long idx = (long)(b * LL + l0 + i) * DI + c;
        xc[idx] = s;
        __nv_bfloat16 h, l2;
        split2(s, h, l2);
        xch[idx] = h;
        xcl[idx] = l2;
    }
}

// ---------------- delta = softplus(dt @ dt_w^T + dt_b), batched --------------------
__global__ void delta_kernel(const float* __restrict__ dbc_base,
                             const float* __restrict__ dwa, const float* __restrict__ dwb,
                             const float* __restrict__ dba, const float* __restrict__ dbb,
                             float* __restrict__ delta_base)
{
    int d   = blockIdx.x * 256 + threadIdx.x;  // [0,DI)
    int m0  = blockIdx.y * 4;
    int dir = blockIdx.z;

    const float* dt_w = dir ? dwb : dwa;
    const float* dt_b = dir ? dbb : dba;
    const float* dbc = dbc_base + (long)dir * MROWS * 64;
    float* delta = delta_base + (long)dir * MROWS * DI;

    float w[DTR];
    const float4* w4 = reinterpret_cast<const float4*>(dt_w + (long)d * DTR);
#pragma unroll
    for (int r = 0; r < DTR / 4; r++) {
        float4 v = w4[r];
        w[4 * r + 0] = v.x; w[4 * r + 1] = v.y; w[4 * r + 2] = v.z; w[4 * r + 3] = v.w;
    }
    float bias = dt_b[d];

#pragma unroll
    for (int mi = 0; mi < 4; mi++) {
        const float* row = dbc + (long)(m0 + mi) * 64;
        float acc = bias;
#pragma unroll
        for (int r = 0; r < DTR; r++) acc = fmaf(row[r], w[r], acc);
        float sp = (acc > 20.f) ? acc : log1pf(__expf(acc));
        delta[(long)(m0 + mi) * DI + d] = sp;
    }
}

// ---------------- scan pass1: chunk-local scan from h=0, batched -------------------
__global__ void scan_pass1_kernel(const float* __restrict__ delta_base,
                                  const float* __restrict__ xc_base,
                                  const float* __restrict__ dbc_base,
                                  const float* __restrict__ Aa_, const float* __restrict__ Ab_,
                                  float* __restrict__ cs_base,
                                  float* __restrict__ he_base)
{
    __shared__ float sB[LC][DS];
    int chunk = blockIdx.x;
    int d     = blockIdx.y * 256 + threadIdx.x;
    int zb    = blockIdx.z;
    int dir   = zb >> 1;
    int b     = zb & 1;
    int m0    = b * LL + chunk * LC;

    const float* A_log = dir ? Ab_ : Aa_;
    const float* delta = delta_base + (long)dir * MROWS * DI;
    const float* xc    = xc_base    + (long)dir * MROWS * DI;
    const float* dbc   = dbc_base   + (long)dir * MROWS * 64;
    float* cs = cs_base + (long)dir * BB * NC * DI;
    float* he = he_base + (long)dir * BB * NC * DI * DS;

    const float* dbc0 = dbc + (long)m0 * 64;
    for (int i = threadIdx.x; i < LC * DS; i += 256) {
        int tt = i >> 4, s = i & 15;
        sB[tt][s] = dbc0[tt * 64 + 32 + s];
    }
    __syncthreads();

    float Aa[DS];
#pragma unroll
    for (int s = 0; s < DS; s++) Aa[s] = -__expf(A_log[d * DS + s]);
    float a0 = Aa[0];
    bool fast = true;
#pragma unroll
    for (int s = 1; s < DS; s++) fast = fast && (fabsf(Aa[s] - (s + 1) * a0) < 1e-4f * fabsf(Aa[s]));

    float h[DS];
#pragma unroll
    for (int s = 0; s < DS; s++) h[s] = 0.f;
    float S = 0.f;

    if (fast) {
        for (int tt = 0; tt < LC; tt++) {
            int m = m0 + tt;
            float dlt = delta[(long)m * DI + d];
            float xcv = xc[(long)m * DI + d];
            S += dlt;
            float du = dlt * xcv;
            float e1 = __expf(dlt * a0);
            float p = e1;
#pragma unroll
            for (int s = 0; s < DS; s++) {
                h[s] = fmaf(h[s], p, du * sB[tt][s]);
                p *= e1;
            }
        }
    } else {
        for (int tt = 0; tt < LC; tt++) {
            int m = m0 + tt;
            float dlt = delta[(long)m * DI + d];
            float xcv = xc[(long)m * DI + d];
            S += dlt;
            float du = dlt * xcv;
#pragma unroll
            for (int s = 0; s < DS; s++) {
                float da = __expf(dlt * Aa[s]);
                h[s] = fmaf(h[s], da, du * sB[tt][s]);
            }
        }
    }

    cs[(long)(b * NC + chunk) * DI + d] = S;
    float* hout = he + ((long)(b * NC + chunk) * DI + d) * DS;
#pragma unroll
    for (int s = 0; s < DS; s++) hout[s] = h[s];
}

// ---------------- scan fixup: sequential over the 16 chunks, batched ---------------
__global__ void scan_fixup_kernel(const float* __restrict__ cs_base,
                                  const float* __restrict__ he_base,
                                  const float* __restrict__ Aa_, const float* __restrict__ Ab_,
                                  float* __restrict__ hs_base)
{
    int idx = blockIdx.x * 256 + threadIdx.x;      // 2*BB*DI*DS threads
    int s = idx & 15;
    int d = (idx >> 4) & (DI - 1);
    int b = (idx >> 14) & 1;
    int dir = idx >> 15;

    const float* A_log = dir ? Ab_ : Aa_;
    const float* cs = cs_base + (long)dir * BB * NC * DI;
    const float* he = he_base + (long)dir * BB * NC * DI * DS;
    float* hs = hs_base + (long)dir * BB * NC * DI * DS;

    float A = -__expf(A_log[d * DS + s]);
    float h = 0.f;
    for (int c = 0; c < NC; c++) {
        long base = ((long)(b * NC + c) * DI + d) * DS + s;
        hs[base] = h;
        float S = cs[(long)(b * NC + c) * DI + d];
        h = __expf(A * S) * h + he[base];
    }
}

// ---------------- scan pass3: replay with h_start, emit gated y, batched -----------
__global__ void scan_pass3_kernel(const float* __restrict__ delta_base,
                                  const float* __restrict__ xc_base,
                                  const float* __restrict__ dbc_base,
                                  const float* __restrict__ Aa_, const float* __restrict__ Ab_,
                                  const float* __restrict__ hs_base,
                                  const float* __restrict__ Da_, const float* __restrict__ Db_,
                                  const float* __restrict__ xz_base,
                                  __nv_bfloat16* __restrict__ ymh_base,
                                  __nv_bfloat16* __restrict__ yml_base)
{
    __shared__ float sB[LC][DS];
    __shared__ float sC[LC][DS];
    int chunk = blockIdx.x;
    int d     = blockIdx.y * 256 + threadIdx.x;
    int zb    = blockIdx.z;
    int dir   = zb >> 1;
    int b     = zb & 1;
    int m0    = b * LL + chunk * LC;

    const float* A_log = dir ? Ab_ : Aa_;
    const float* Dp    = dir ? Db_ : Da_;
    const float* delta = delta_base + (long)dir * MROWS * DI;
    const float* xc    = xc_base    + (long)dir * MROWS * DI;
    const float* dbc   = dbc_base   + (long)dir * MROWS * 64;
    const float* hs    = hs_base    + (long)dir * BB * NC * DI * DS;
    const float* xz    = xz_base    + (long)dir * MROWS * E2;
    __nv_bfloat16* ymh = ymh_base + (long)dir * MROWS * DI;
    __nv_bfloat16* yml = yml_base + (long)dir * MROWS * DI;

    const float* dbc0 = dbc + (long)m0 * 64;
    for (int i = threadIdx.x; i < LC * DS; i += 256) {
        int tt = i >> 4, s = i & 15;
        sB[tt][s] = dbc0[tt * 64 + 32 + s];
        sC[tt][s] = dbc0[tt * 64 + 48 + s];
    }
    __syncthreads();

    float Aa[DS];
#pragma unroll
    for (int s = 0; s < DS; s++) Aa[s] = -__expf(A_log[d * DS + s]);
    float a0 = Aa[0];
    bool fast = true;
#pragma unroll
    for (int s = 1; s < DS; s++) fast = fast && (fabsf(Aa[s] - (s + 1) * a0) < 1e-4f * fabsf(Aa[s]));

    float h[DS];
    const float* hin = hs + ((long)(b * NC + chunk) * DI + d) * DS;
#pragma unroll
    for (int s = 0; s < DS; s++) h[s] = hin[s];

    float Dv = Dp[d];

    for (int tt = 0; tt < LC; tt++) {
        int m = m0 + tt;
        float dlt = delta[(long)m * DI + d];
        float xcv = xc[(long)m * DI + d];
        float du = dlt * xcv;
        float y = 0.f;
        if (fast) {
            float e1 = __expf(dlt * a0);
            float p = e1;
#pragma unroll
            for (int s = 0; s < DS; s++) {
                h[s] = fmaf(h[s], p, du * sB[tt][s]);
                y = fmaf(h[s], sC[tt][s], y);
                p *= e1;
            }
        } else {
#pragma unroll
            for (int s = 0; s < DS; s++) {
                float da = __expf(dlt * Aa[s]);
                h[s] = fmaf(h[s], da, du * sB[tt][s]);
                y = fmaf(h[s], sC[tt][s], y);
            }
        }
        float z = xz[(long)m * E2 + DI + d];
        float sil = z / (1.f + __expf(-z));
        float out = (y + xcv * Dv) * sil;
        __nv_bfloat16 hh, ll;
        split2(out, hh, ll);
        long idx = (long)m * DI + d;
        ymh[idx] = hh;
        yml[idx] = ll;
    }
}

// ---------------- host launcher ---------------------------------------------------
extern "C" void kernel_launch(void* const* d_in, const int* in_sizes, int n_in,
                              void* d_out, int out_size)
{
    const float* x = (const float*)d_in[0];
    float* out = (float*)d_out;

    float *xz, *xc, *dbc, *part, *delta, *cs, *he, *hs;
    cudaGetSymbolAddress((void**)&xz,    g_xz);
    cudaGetSymbolAddress((void**)&xc,    g_xc);
    cudaGetSymbolAddress((void**)&dbc,   g_dbc);
    cudaGetSymbolAddress((void**)&part,  g_part);
    cudaGetSymbolAddress((void**)&delta, g_delta);
    cudaGetSymbolAddress((void**)&cs,    g_cs);
    cudaGetSymbolAddress((void**)&he,    g_he);
    cudaGetSymbolAddress((void**)&hs,    g_hs);

    __nv_bfloat16 *xbh, *xbl, *w1h, *w1l, *wxh, *wxl, *woh, *wol, *xch, *xcl, *ymh, *yml;
    cudaGetSymbolAddress((void**)&xbh, g_xbh);
    cudaGetSymbolAddress((void**)&xbl, g_xbl);
    cudaGetSymbolAddress((void**)&w1h, g_w1h);
    cudaGetSymbolAddress((void**)&w1l, g_w1l);
    cudaGetSymbolAddress((void**)&wxh, g_wxh);
    cudaGetSymbolAddress((void**)&wxl, g_wxl);
    cudaGetSymbolAddress((void**)&woh, g_woh);
    cudaGetSymbolAddress((void**)&wol, g_wol);
    cudaGetSymbolAddress((void**)&xch, g_xch);
    cudaGetSymbolAddress((void**)&xcl, g_xcl);
    cudaGetSymbolAddress((void**)&ymh, g_ymh);
    cudaGetSymbolAddress((void**)&yml, g_yml);

    // per-direction input pointers
    const float* in_w[2];  const float* conv_w[2]; const float* conv_b[2];
    const float* xproj_w[2]; const float* dt_w[2]; const float* dt_b[2];
    const float* A_log[2]; const float* Dp[2];     const float* out_w[2];
    for (int dir = 0; dir < 2; dir++) {
        in_w[dir]    = (const float*)d_in[1 + dir * 9 + 0];
        conv_w[dir]  = (const float*)d_in[1 + dir * 9 + 1];
        conv_b[dir]  = (const float*)d_in[1 + dir * 9 + 2];
        xproj_w[dir] = (const float*)d_in[1 + dir * 9 + 3];
        dt_w[dir]    = (const float*)d_in[1 + dir * 9 + 4];
        dt_b[dir]    = (const float*)d_in[1 + dir * 9 + 5];
        A_log[dir]   = (const float*)d_in[1 + dir * 9 + 6];
        Dp[dir]      = (const float*)d_in[1 + dir * 9 + 7];
        out_w[dir]   = (const float*)d_in[1 + dir * 9 + 8];
    }

    const long HID = (long)MROWS * DIM;
    const int NW = (E2 * DM / 4) + (64 * DI / 4) + (DM * DI / 4);

    // 1) fused residual copy + x bf16 split; weight splits (both dirs)
    prep_x_kernel<<<(MROWS * DIM / 4 + 255) / 256, 256>>>(x, out + HID, xbh, xbl, MROWS * DIM / 4);
    split_weights_kernel<<<dim3((NW + 255) / 256, 2), 256>>>(
        in_w[0], in_w[1], xproj_w[0], xproj_w[1], out_w[0], out_w[1],
        w1h, w1l, wxh, wxl, woh, wol);

    // 2) xz[dir] = x_dir @ in_w[dir]^T   (M=4096, N=2048, K=512), both dirs
    mma_gemm_kernel<128, 128, 64, 32><<<dim3(E2 / 128, MROWS / 128, 2), 256>>>(
        xbh, xbl, w1h, w1l, xz, DM, 1,
        /*lda*/ DIM, /*a_dstride*/ 0, /*acol0_step*/ DM, /*flip_is_dir*/ 1,
        /*ldb*/ DM, /*b_dstride*/ (long)E2 * DM,
        /*ldc*/ E2, /*c_dstride*/ (long)MROWS * E2, /*ccol0_step*/ 0, 0);

    // 3) conv + silu, both dirs
    conv_silu_kernel<<<dim3(DI / 256, LL / 8, 2 * BB), 256>>>(
        xz, conv_w[0], conv_w[1], conv_b[0], conv_b[1], xc, xch, xcl);

    // 4) dbc = xc @ xproj_w^T  (split-K=4), both dirs + reduce
    mma_gemm_kernel<64, 64, 32, 32><<<dim3(1, MROWS / 64, 2 * KSPLIT), 128>>>(
        xch, xcl, wxh, wxl, part, DI / KSPLIT, KSPLIT,
        DI, (long)MROWS * DI, 0, 0,
        DI, (long)64 * DI,
        64, (long)KSPLIT * MROWS * 64, 0, (long)MROWS * 64);
    reduce_partials_kernel<<<(2 * MROWS * 64 / 4 + 255) / 256, 256>>>(part, dbc);

    // 5) delta, both dirs
    delta_kernel<<<dim3(DI / 256, MROWS / 4, 2), 256>>>(
        dbc, dt_w[0], dt_w[1], dt_b[0], dt_b[1], delta);

    // 6-8) chunked parallel scan, both dirs
    scan_pass1_kernel<<<dim3(NC, DI / 256, 2 * BB), 256>>>(
        delta, xc, dbc, A_log[0], A_log[1], cs, he);
    scan_fixup_kernel<<<(2 * BB * DI * DS) / 256, 256>>>(
        cs, he, A_log[0], A_log[1], hs);
    scan_pass3_kernel<<<dim3(NC, DI / 256, 2 * BB), 256>>>(
        delta, xc, dbc, A_log[0], A_log[1], hs, Dp[0], Dp[1], xz, ymh, yml);

    // 9) hidden[:, :, dir*512:+512] = ym @ out_w^T  (M=4096, N=512, K=1024), both dirs
    mma_gemm_kernel<128, 128, 64, 32><<<dim3(DM / 128, MROWS / 128, 2), 256>>>(
        ymh, yml, woh, wol, out, DI, 1,
        DI, (long)MROWS * DI, 0, 0,
        DI, (long)DM * DI,
        DIM, 0, DM, 0);
}

// round 6
// speedup vs baseline: 2.9957x; 1.1008x over previous
#include <cuda_runtime.h>
#include <cuda_bf16.h>
#include <cuda_fp16.h>
#include <cstdint>

// Problem constants
#define BB    2
#define LL    2048
#define DIM   1024
#define DM    512
#define DI    1024
#define E2    2048      // 2*DI
#define MROWS 4096      // BB*LL
#define DS    16        // D_STATE
#define DTR   32        // DT_RANK
#define NC    16        // scan chunks
#define LC    128       // chunk length (NC*LC == LL)
#define KSPLIT 4        // split-K factor for xproj GEMM

// ---------------- scratch (static device memory; no allocation allowed) ----------
__device__ float g_xz   [2][MROWS * E2];       // in-proj output (xh | z)
__device__ float g_xc   [2][MROWS * DI];       // conv+silu output (fp32 for scan)
__device__ float g_dbc  [2][MROWS * 64];       // x-proj output (dt|B|C)
__device__ float g_part [2][KSPLIT][MROWS * 64]; // split-K partials for xproj
__device__ float g_delta[2][MROWS * DI];       // softplus(dt @ dt_w^T + dt_b)
__device__ float g_cs   [2][BB * NC * DI];            // per-chunk sum of delta
__device__ float g_he   [2][BB * NC * DI * DS];       // chunk-local h_end
__device__ float g_hs   [2][BB * NC * DI * DS];       // chunk h_start (after fixup)

// bf16 hi/lo split operands for tensor-core GEMMs (GEMM1, xproj)
__device__ __nv_bfloat16 g_xbh [MROWS * DIM];
__device__ __nv_bfloat16 g_xbl [MROWS * DIM];
__device__ __nv_bfloat16 g_w1h [2][E2 * DM];
__device__ __nv_bfloat16 g_w1l [2][E2 * DM];
__device__ __nv_bfloat16 g_wxh [2][64 * DI];
__device__ __nv_bfloat16 g_wxl [2][64 * DI];
__device__ __nv_bfloat16 g_xch [2][MROWS * DI];
__device__ __nv_bfloat16 g_xcl [2][MROWS * DI];

// single-fp16 operands for GEMM3 (out-proj; error lands directly in output)
__device__ __half g_wof [2][DM * DI];
__device__ __half g_ymf [2][MROWS * DI];

// ---------------- helpers ----------------------------------------------------------
__device__ __forceinline__ void split2(float v, __nv_bfloat16& h, __nv_bfloat16& l) {
    h = __float2bfloat16(v);
    l = __float2bfloat16(v - __bfloat162float(h));
}

__device__ __forceinline__ void mma_bf16(float* c, const uint32_t* a, const uint32_t* b) {
    asm volatile(
        "mma.sync.aligned.m16n8k16.row.col.f32.bf16.bf16.f32 "
        "{%0,%1,%2,%3}, {%4,%5,%6,%7}, {%8,%9}, {%0,%1,%2,%3};\n"
        : "+f"(c[0]), "+f"(c[1]), "+f"(c[2]), "+f"(c[3])
        : "r"(a[0]), "r"(a[1]), "r"(a[2]), "r"(a[3]), "r"(b[0]), "r"(b[1]));
}

__device__ __forceinline__ void mma_f16(float* c, const uint32_t* a, const uint32_t* b) {
    asm volatile(
        "mma.sync.aligned.m16n8k16.row.col.f32.f16.f16.f32 "
        "{%0,%1,%2,%3}, {%4,%5,%6,%7}, {%8,%9}, {%0,%1,%2,%3};\n"
        : "+f"(c[0]), "+f"(c[1]), "+f"(c[2]), "+f"(c[3])
        : "r"(a[0]), "r"(a[1]), "r"(a[2]), "r"(a[3]), "r"(b[0]), "r"(b[1]));
}

__device__ __forceinline__ void ldsm_x4(uint32_t& r0, uint32_t& r1, uint32_t& r2, uint32_t& r3, uint32_t a) {
    asm volatile("ldmatrix.sync.aligned.m8n8.x4.shared.b16 {%0,%1,%2,%3}, [%4];"
                 : "=r"(r0), "=r"(r1), "=r"(r2), "=r"(r3) : "r"(a));
}

#define CPASYNC16(dst, src) asm volatile("cp.async.cg.shared.global [%0], [%1], 16;\n" :: "r"(dst), "l"(src))
#define CPCOMMIT()          asm volatile("cp.async.commit_group;\n")
#define CPWAIT1()           asm volatile("cp.async.wait_group 1;\n")

__device__ __forceinline__ uint32_t smem_u32(const void* p) {
    return (uint32_t)__cvta_generic_to_shared(p);
}

// ---------------- split fp32 -> bf16 hi/lo (vectorized float4) ---------------------
__device__ __forceinline__ void split_body(const float* __restrict__ in,
                                           __nv_bfloat16* __restrict__ hi,
                                           __nv_bfloat16* __restrict__ lo, int i)
{
    float4 v = reinterpret_cast<const float4*>(in)[i];
    float vv[4] = {v.x, v.y, v.z, v.w};
    __nv_bfloat16 h[4], l[4];
#pragma unroll
    for (int k = 0; k < 4; k++) split2(vv[k], h[k], l[k]);
    __nv_bfloat162* hp = reinterpret_cast<__nv_bfloat162*>(hi) + 2 * i;
    __nv_bfloat162* lp = reinterpret_cast<__nv_bfloat162*>(lo) + 2 * i;
    __nv_bfloat162 t;
    t.x = h[0]; t.y = h[1]; hp[0] = t;
    t.x = h[2]; t.y = h[3]; hp[1] = t;
    t.x = l[0]; t.y = l[1]; lp[0] = t;
    t.x = l[2]; t.y = l[3]; lp[1] = t;
}

// single fp16 conversion (vectorized)
__device__ __forceinline__ void half_body(const float* __restrict__ in,
                                          __half* __restrict__ o, int i)
{
    float4 v = reinterpret_cast<const float4*>(in)[i];
    __half2* op = reinterpret_cast<__half2*>(o) + 2 * i;
    op[0] = __floats2half2_rn(v.x, v.y);
    op[1] = __floats2half2_rn(v.z, v.w);
}

// Fused: residual copy + x -> bf16 hi/lo split (x read once)
__global__ void prep_x_kernel(const float* __restrict__ x,
                              float* __restrict__ resid,
                              __nv_bfloat16* __restrict__ hi,
                              __nv_bfloat16* __restrict__ lo, int n4)
{
    int i = blockIdx.x * 256 + threadIdx.x;
    if (i >= n4) return;
    float4 v = reinterpret_cast<const float4*>(x)[i];
    reinterpret_cast<float4*>(resid)[i] = v;
    float vv[4] = {v.x, v.y, v.z, v.w};
    __nv_bfloat16 h[4], l[4];
#pragma unroll
    for (int k = 0; k < 4; k++) split2(vv[k], h[k], l[k]);
    __nv_bfloat162* hp = reinterpret_cast<__nv_bfloat162*>(hi) + 2 * i;
    __nv_bfloat162* lp = reinterpret_cast<__nv_bfloat162*>(lo) + 2 * i;
    __nv_bfloat162 t;
    t.x = h[0]; t.y = h[1]; hp[0] = t;
    t.x = h[2]; t.y = h[3]; hp[1] = t;
    t.x = l[0]; t.y = l[1]; lp[0] = t;
    t.x = l[2]; t.y = l[3]; lp[1] = t;
}

// Batched per-direction weight conversions, both dirs, one launch.
// in_w/xproj_w -> bf16 hi/lo; out_w -> single fp16.
__global__ void split_weights_kernel(const float* __restrict__ w1a, const float* __restrict__ w1b,
                                     const float* __restrict__ wxa, const float* __restrict__ wxb,
                                     const float* __restrict__ woa, const float* __restrict__ wob,
                                     __nv_bfloat16* __restrict__ w1h, __nv_bfloat16* __restrict__ w1l,
                                     __nv_bfloat16* __restrict__ wxh, __nv_bfloat16* __restrict__ wxl,
                                     __half* __restrict__ wof)
{
    const int N1 = E2 * DM / 4;
    const int N2 = 64 * DI / 4;
    const int N3 = DM * DI / 4;
    int dir = blockIdx.y;
    const float* w1 = dir ? w1b : w1a;
    const float* wx = dir ? wxb : wxa;
    const float* wo = dir ? wob : woa;
    int i = blockIdx.x * 256 + threadIdx.x;
    if (i < N1) { split_body(w1, w1h + (long)dir * E2 * DM, w1l + (long)dir * E2 * DM, i); return; }
    i -= N1;
    if (i < N2) { split_body(wx, wxh + (long)dir * 64 * DI, wxl + (long)dir * 64 * DI, i); return; }
    i -= N2;
    if (i < N3) { half_body(wo, wof + (long)dir * DM * DI, i); }
}

// ---------------- tensor-core NT GEMM, ldmatrix + 3-stage cp.async -----------------
// TERMS=3: C = Ahi*Bhi + Ahi*Blo + Alo*Bhi (bf16 hi/lo).  TERMS=1: C = A*B (single).
// FP16=1 uses f16 mma, else bf16. Batched over blockIdx.z = dir*nks + kz.
template<int BM, int BN, int WM, int WN, int TERMS, int FP16>
__global__ void __launch_bounds__((BM / WM) * (BN / WN) * 32)
mma_gemm_kernel(const __nv_bfloat16* __restrict__ Ahi, const __nv_bfloat16* __restrict__ Alo,
                const __nv_bfloat16* __restrict__ Bhi, const __nv_bfloat16* __restrict__ Blo,
                float* __restrict__ C, int ksplit, int nks,
                int lda, long a_dstride, int acol0_step, int flip_is_dir,
                int ldb, long b_dstride,
                int ldc, long c_dstride, int ccol0_step, long csplit_stride)
{
    constexpr int THREADS = (BM / WM) * (BN / WN) * 32;
    constexpr int WM16 = WM / 16;
    constexpr int WN8  = WN / 8;
    constexpr int NCOMP = (TERMS == 1) ? 1 : 2;

    __shared__ __align__(16) uint8_t As[3 * NCOMP * BM * 32];   // [stage][comp][BM][32B]
    __shared__ __align__(16) uint8_t Bs[3 * NCOMP * BN * 32];

    const int tid  = threadIdx.x;
    const int bm0  = blockIdx.y * BM;
    const int bn0  = blockIdx.x * BN;
    const int z    = blockIdx.z;
    const int dir  = z / nks;
    const int kz   = z - dir * nks;
    const int kbeg = kz * ksplit;
    const int KT   = ksplit / 16;

    const __nv_bfloat16* Ahp = Ahi + (long)dir * a_dstride;
    const __nv_bfloat16* Alp = Alo ? Alo + (long)dir * a_dstride : nullptr;
    const __nv_bfloat16* Bhp = Bhi + (long)dir * b_dstride;
    const __nv_bfloat16* Blp = Blo ? Blo + (long)dir * b_dstride : nullptr;
    const int acol0 = dir * acol0_step;
    const int ccol0 = dir * ccol0_step;
    const int flip  = flip_is_dir ? dir : 0;
    C += (long)dir * c_dstride + (long)kz * csplit_stride;

    const int wid  = tid >> 5;
    const int lane = tid & 31;
    const int wm   = wid / (BN / WN);
    const int wn   = wid % (BN / WN);
    const int g    = lane >> 2;
    const int t    = lane & 3;

    float acc[WM16][WN8][4];
#pragma unroll
    for (int i = 0; i < WM16; i++)
#pragma unroll
        for (int j = 0; j < WN8; j++)
#pragma unroll
            for (int q = 0; q < 4; q++) acc[i][j][q] = 0.f;

    auto loadA = [&](int st, int k0) {
        for (int i = tid; i < BM * 2 * NCOMP; i += THREADS) {
            int comp = i / (BM * 2);
            int rem  = i - comp * BM * 2;
            int r = rem >> 1;
            int c = rem & 1;
            int mg = bm0 + r;
            int rowg = mg;
            if (flip) { int b = mg >> 11; int l = mg & 2047; rowg = (b << 11) + (2047 - l); }
            const __nv_bfloat16* src = (comp ? Alp : Ahp) + (long)rowg * lda + acol0 + k0 + c * 8;
            uint32_t dst = smem_u32(As + ((st * NCOMP + comp) * BM + r) * 32 + ((c ^ ((r >> 2) & 1)) << 4));
            CPASYNC16(dst, src);
        }
    };
    auto loadB = [&](int st, int k0) {
        for (int i = tid; i < BN * 2 * NCOMP; i += THREADS) {
            int comp = i / (BN * 2);
            int rem  = i - comp * BN * 2;
            int r = rem >> 1;
            int c = rem & 1;
            const __nv_bfloat16* src = (comp ? Blp : Bhp) + (long)(bn0 + r) * ldb + k0 + c * 8;
            uint32_t dst = smem_u32(Bs + ((st * NCOMP + comp) * BN + r) * 32 + ((c ^ ((r >> 2) & 1)) << 4));
            CPASYNC16(dst, src);
        }
    };

    const int a_tile   = lane >> 3;
    const int a_rowoff = ((a_tile & 1) << 3) + (lane & 7);
    const int a_chunk  = a_tile >> 1;
    const int b_rowoff = (((lane >> 4) & 1) << 3) + (lane & 7);
    const int b_chunk  = (lane >> 3) & 1;

    // prologue: stages 0 and 1
    loadA(0, kbeg); loadB(0, kbeg); CPCOMMIT();
    if (KT > 1) { loadA(1, kbeg + 16); loadB(1, kbeg + 16); }
    CPCOMMIT();

    for (int kt = 0; kt < KT; kt++) {
        CPWAIT1();
        __syncthreads();

        if (kt + 2 < KT) { loadA((kt + 2) % 3, kbeg + (kt + 2) * 16); loadB((kt + 2) % 3, kbeg + (kt + 2) * 16); }
        CPCOMMIT();

        const int st = kt % 3;
        const uint8_t* Ah = As + (st * NCOMP + 0) * BM * 32;
        const uint8_t* Bh = Bs + (st * NCOMP + 0) * BN * 32;
        const uint8_t* Al = As + (st * NCOMP + (NCOMP - 1)) * BM * 32;
        const uint8_t* Bl = Bs + (st * NCOMP + (NCOMP - 1)) * BN * 32;

        uint32_t ah[WM16][4], al[WM16][4], bh[WN8][2], bl[WN8][2];
#pragma unroll
        for (int i = 0; i < WM16; i++) {
            int r = wm * WM + i * 16 + a_rowoff;
            uint32_t off = r * 32 + (((a_chunk ^ ((r >> 2) & 1))) << 4);
            ldsm_x4(ah[i][0], ah[i][1], ah[i][2], ah[i][3], smem_u32(Ah + off));
            if (TERMS == 3) ldsm_x4(al[i][0], al[i][1], al[i][2], al[i][3], smem_u32(Al + off));
        }
#pragma unroll
        for (int jp = 0; jp < WN8 / 2; jp++) {
            int r = wn * WN + jp * 16 + b_rowoff;
            uint32_t off = r * 32 + (((b_chunk ^ ((r >> 2) & 1))) << 4);
            ldsm_x4(bh[2 * jp][0], bh[2 * jp][1], bh[2 * jp + 1][0], bh[2 * jp + 1][1], smem_u32(Bh + off));
            if (TERMS == 3) ldsm_x4(bl[2 * jp][0], bl[2 * jp][1], bl[2 * jp + 1][0], bl[2 * jp + 1][1], smem_u32(Bl + off));
        }
#pragma unroll
        for (int i = 0; i < WM16; i++)
#pragma unroll
            for (int j = 0; j < WN8; j++) {
                if (FP16) {
                    mma_f16(acc[i][j], ah[i], bh[j]);
                    if (TERMS == 3) { mma_f16(acc[i][j], ah[i], bl[j]); mma_f16(acc[i][j], al[i], bh[j]); }
                } else {
                    mma_bf16(acc[i][j], ah[i], bh[j]);
                    if (TERMS == 3) { mma_bf16(acc[i][j], ah[i], bl[j]); mma_bf16(acc[i][j], al[i], bh[j]); }
                }
            }
    }

    // epilogue: fp32 direct store (cols 2t,2t+1 contiguous -> float2)
#pragma unroll
    for (int i = 0; i < WM16; i++) {
#pragma unroll
        for (int j = 0; j < WN8; j++) {
            int r  = bm0 + wm * WM + i * 16 + g;
            int n0 = bn0 + ccol0 + wn * WN + j * 8 + 2 * t;
            float2 v0 = make_float2(acc[i][j][0], acc[i][j][1]);
            float2 v1 = make_float2(acc[i][j][2], acc[i][j][3]);
            *reinterpret_cast<float2*>(&C[(long)r * ldc + n0])       = v0;
            *reinterpret_cast<float2*>(&C[(long)(r + 8) * ldc + n0]) = v1;
        }
    }
}

// ---------------- split-K reduction: dbc[dir] = sum_z part[dir][z], both dirs ------
__global__ void reduce_partials_kernel(const float* __restrict__ part, float* __restrict__ dbc)
{
    const int n4 = MROWS * 64 / 4;             // per-dir float4 count
    int i = blockIdx.x * 256 + threadIdx.x;    // over 2*n4
    if (i >= 2 * n4) return;
    int dir = i / n4;
    int j = i - dir * n4;
    const float* p = part + (long)dir * KSPLIT * MROWS * 64;
    float4 a = reinterpret_cast<const float4*>(p)[j];
#pragma unroll
    for (int z = 1; z < KSPLIT; z++) {
        float4 b = reinterpret_cast<const float4*>(p + (long)z * MROWS * 64)[j];
        a.x += b.x; a.y += b.y; a.z += b.z; a.w += b.w;
    }
    reinterpret_cast<float4*>(dbc + (long)dir * MROWS * 64)[j] = a;
}

// ---------------- depthwise causal conv(4) + silu (+ bf16 split out), batched ------
__global__ void conv_silu_kernel(const float* __restrict__ xz_base,
                                 const float* __restrict__ cwa, const float* __restrict__ cwb,
                                 const float* __restrict__ cba, const float* __restrict__ cbb,
                                 float* __restrict__ xc_base,
                                 __nv_bfloat16* __restrict__ xch_base,
                                 __nv_bfloat16* __restrict__ xcl_base)
{
    int c  = blockIdx.x * blockDim.x + threadIdx.x;   // channel in [0,DI)
    int l0 = blockIdx.y * 8;
    int zb = blockIdx.z;
    int dir = zb >> 1;
    int b   = zb & 1;

    const float* cw = dir ? cwb : cwa;
    const float* cb = dir ? cbb : cba;
    const float* xz = xz_base + (long)dir * MROWS * E2;
    float* xc = xc_base + (long)dir * MROWS * DI;
    __nv_bfloat16* xch = xch_base + (long)dir * MROWS * DI;
    __nv_bfloat16* xcl = xcl_base + (long)dir * MROWS * DI;

    float w0 = cw[c * 4 + 0], w1 = cw[c * 4 + 1], w2 = cw[c * 4 + 2], w3 = cw[c * 4 + 3];
    float bias = cb[c];

    float v[11];
#pragma unroll
    for (int j = 0; j < 11; j++) {
        int l = l0 - 3 + j;
        v[j] = (l >= 0) ? xz[(long)(b * LL + l) * E2 + c] : 0.f;
    }
#pragma unroll
    for (int i = 0; i < 8; i++) {
        float a = v[i] * w0 + v[i + 1] * w1 + v[i + 2] * w2 + v[i + 3] * w3 + bias;
        float s = a / (1.f + __expf(-a));   // silu
        long idx = (long)(b * LL + l0 + i) * DI + c;
        xc[idx] = s;
        __nv_bfloat16 h, l2;
        split2(s, h, l2);
        xch[idx] = h;
        xcl[idx] = l2;
    }
}

// ---------------- delta = softplus(dt @ dt_w^T + dt_b), batched --------------------
__global__ void delta_kernel(const float* __restrict__ dbc_base,
                             const float* __restrict__ dwa, const float* __restrict__ dwb,
                             const float* __restrict__ dba, const float* __restrict__ dbb,
                             float* __restrict__ delta_base)
{
    int d   = blockIdx.x * 256 + threadIdx.x;  // [0,DI)
    int m0  = blockIdx.y * 4;
    int dir = blockIdx.z;

    const float* dt_w = dir ? dwb : dwa;
    const float* dt_b = dir ? dbb : dba;
    const float* dbc = dbc_base + (long)dir * MROWS * 64;
    float* delta = delta_base + (long)dir * MROWS * DI;

    float w[DTR];
    const float4* w4 = reinterpret_cast<const float4*>(dt_w + (long)d * DTR);
#pragma unroll
    for (int r = 0; r < DTR / 4; r++) {
        float4 v = w4[r];
        w[4 * r + 0] = v.x; w[4 * r + 1] = v.y; w[4 * r + 2] = v.z; w[4 * r + 3] = v.w;
    }
    float bias = dt_b[d];

#pragma unroll
    for (int mi = 0; mi < 4; mi++) {
        const float* row = dbc + (long)(m0 + mi) * 64;
        float acc = bias;
#pragma unroll
        for (int r = 0; r < DTR; r++) acc = fmaf(row[r], w[r], acc);
        float sp = (acc > 20.f) ? acc : log1pf(__expf(acc));
        delta[(long)(m0 + mi) * DI + d] = sp;
    }
}

// ---------------- scan pass1: chunk-local scan from h=0, batched -------------------
__global__ void scan_pass1_kernel(const float* __restrict__ delta_base,
                                  const float* __restrict__ xc_base,
                                  const float* __restrict__ dbc_base,
                                  const float* __restrict__ Aa_, const float* __restrict__ Ab_,
                                  float* __restrict__ cs_base,
                                  float* __restrict__ he_base)
{
    __shared__ float sB[LC][DS];
    int chunk = blockIdx.x;
    int d     = blockIdx.y * 256 + threadIdx.x;
    int zb    = blockIdx.z;
    int dir   = zb >> 1;
    int b     = zb & 1;
    int m0    = b * LL + chunk * LC;

    const float* A_log = dir ? Ab_ : Aa_;
    const float* delta = delta_base + (long)dir * MROWS * DI;
    const float* xc    = xc_base    + (long)dir * MROWS * DI;
    const float* dbc   = dbc_base   + (long)dir * MROWS * 64;
    float* cs = cs_base + (long)dir * BB * NC * DI;
    float* he = he_base + (long)dir * BB * NC * DI * DS;

    const float* dbc0 = dbc + (long)m0 * 64;
    for (int i = threadIdx.x; i < LC * DS; i += 256) {
        int tt = i >> 4, s = i & 15;
        sB[tt][s] = dbc0[tt * 64 + 32 + s];
    }
    __syncthreads();

    float Aa[DS];
#pragma unroll
    for (int s = 0; s < DS; s++) Aa[s] = -__expf(A_log[d * DS + s]);
    float a0 = Aa[0];
    bool fast = true;
#pragma unroll
    for (int s = 1; s < DS; s++) fast = fast && (fabsf(Aa[s] - (s + 1) * a0) < 1e-4f * fabsf(Aa[s]));

    float h[DS];
#pragma unroll
    for (int s = 0; s < DS; s++) h[s] = 0.f;
    float S = 0.f;

    if (fast) {
        for (int tt = 0; tt < LC; tt++) {
            int m = m0 + tt;
            float dlt = delta[(long)m * DI + d];
            float xcv = xc[(long)m * DI + d];
            S += dlt;
            float du = dlt * xcv;
            float e1 = __expf(dlt * a0);
            float p = e1;
#pragma unroll
            for (int s = 0; s < DS; s++) {
                h[s] = fmaf(h[s], p, du * sB[tt][s]);
                p *= e1;
            }
        }
    } else {
        for (int tt = 0; tt < LC; tt++) {
            int m = m0 + tt;
            float dlt = delta[(long)m * DI + d];
            float xcv = xc[(long)m * DI + d];
            S += dlt;
            float du = dlt * xcv;
#pragma unroll
            for (int s = 0; s < DS; s++) {
                float da = __expf(dlt * Aa[s]);
                h[s] = fmaf(h[s], da, du * sB[tt][s]);
            }
        }
    }

    cs[(long)(b * NC + chunk) * DI + d] = S;
    float* hout = he + ((long)(b * NC + chunk) * DI + d) * DS;
#pragma unroll
    for (int s = 0; s < DS; s++) hout[s] = h[s];
}

// ---------------- scan fixup: sequential over the 16 chunks, batched ---------------
__global__ void scan_fixup_kernel(const float* __restrict__ cs_base,
                                  const float* __restrict__ he_base,
                                  const float* __restrict__ Aa_, const float* __restrict__ Ab_,
                                  float* __restrict__ hs_base)
{
    int idx = blockIdx.x * 256 + threadIdx.x;      // 2*BB*DI*DS threads
    int s = idx & 15;
    int d = (idx >> 4) & (DI - 1);
    int b = (idx >> 14) & 1;
    int dir = idx >> 15;

    const float* A_log = dir ? Ab_ : Aa_;
    const float* cs = cs_base + (long)dir * BB * NC * DI;
    const float* he = he_base + (long)dir * BB * NC * DI * DS;
    float* hs = hs_base + (long)dir * BB * NC * DI * DS;

    float A = -__expf(A_log[d * DS + s]);
    float h = 0.f;
    for (int c = 0; c < NC; c++) {
        long base = ((long)(b * NC + c) * DI + d) * DS + s;
        hs[base] = h;
        float S = cs[(long)(b * NC + c) * DI + d];
        h = __expf(A * S) * h + he[base];
    }
}

// ---------------- scan pass3: replay with h_start, emit gated y (single fp16) ------
__global__ void scan_pass3_kernel(const float* __restrict__ delta_base,
                                  const float* __restrict__ xc_base,
                                  const float* __restrict__ dbc_base,
                                  const float* __restrict__ Aa_, const float* __restrict__ Ab_,
                                  const float* __restrict__ hs_base,
                                  const float* __restrict__ Da_, const float* __restrict__ Db_,
                                  const float* __restrict__ xz_base,
                                  __half* __restrict__ ymf_base)
{
    __shared__ float sB[LC][DS];
    __shared__ float sC[LC][DS];
    int chunk = blockIdx.x;
    int d     = blockIdx.y * 256 + threadIdx.x;
    int zb    = blockIdx.z;
    int dir   = zb >> 1;
    int b     = zb & 1;
    int m0    = b * LL + chunk * LC;

    const float* A_log = dir ? Ab_ : Aa_;
    const float* Dp    = dir ? Db_ : Da_;
    const float* delta = delta_base + (long)dir * MROWS * DI;
    const float* xc    = xc_base    + (long)dir * MROWS * DI;
    const float* dbc   = dbc_base   + (long)dir * MROWS * 64;
    const float* hs    = hs_base    + (long)dir * BB * NC * DI * DS;
    const float* xz    = xz_base    + (long)dir * MROWS * E2;
    __half* ymf = ymf_base + (long)dir * MROWS * DI;

    const float* dbc0 = dbc + (long)m0 * 64;
    for (int i = threadIdx.x; i < LC * DS; i += 256) {
        int tt = i >> 4, s = i & 15;
        sB[tt][s] = dbc0[tt * 64 + 32 + s];
        sC[tt][s] = dbc0[tt * 64 + 48 + s];
    }
    __syncthreads();

    float Aa[DS];
#pragma unroll
    for (int s = 0; s < DS; s++) Aa[s] = -__expf(A_log[d * DS + s]);
    float a0 = Aa[0];
    bool fast = true;
#pragma unroll
    for (int s = 1; s < DS; s++) fast = fast && (fabsf(Aa[s] - (s + 1) * a0) < 1e-4f * fabsf(Aa[s]));

    float h[DS];
    const float* hin = hs + ((long)(b * NC + chunk) * DI + d) * DS;
#pragma unroll
    for (int s = 0; s < DS; s++) h[s] = hin[s];

    float Dv = Dp[d];

    for (int tt = 0; tt < LC; tt++) {
        int m = m0 + tt;
        float dlt = delta[(long)m * DI + d];
        float xcv = xc[(long)m * DI + d];
        float du = dlt * xcv;
        float y = 0.f;
        if (fast) {
            float e1 = __expf(dlt * a0);
            float p = e1;
#pragma unroll
            for (int s = 0; s < DS; s++) {
                h[s] = fmaf(h[s], p, du * sB[tt][s]);
                y = fmaf(h[s], sC[tt][s], y);
                p *= e1;
            }
        } else {
#pragma unroll
            for (int s = 0; s < DS; s++) {
                float da = __expf(dlt * Aa[s]);
                h[s] = fmaf(h[s], da, du * sB[tt][s]);
                y = fmaf(h[s], sC[tt][s], y);
            }
        }
        float z = xz[(long)m * E2 + DI + d];
        float sil = z / (1.f + __expf(-z));
        float out = (y + xcv * Dv) * sil;
        ymf[(long)m * DI + d] = __float2half(out);
    }
}

// ---------------- host launcher ---------------------------------------------------
extern "C" void kernel_launch(void* const* d_in, const int* in_sizes, int n_in,
                              void* d_out, int out_size)
{
    const float* x = (const float*)d_in[0];
    float* out = (float*)d_out;

    float *xz, *xc, *dbc, *part, *delta, *cs, *he, *hs;
    cudaGetSymbolAddress((void**)&xz,    g_xz);
    cudaGetSymbolAddress((void**)&xc,    g_xc);
    cudaGetSymbolAddress((void**)&dbc,   g_dbc);
    cudaGetSymbolAddress((void**)&part,  g_part);
    cudaGetSymbolAddress((void**)&delta, g_delta);
    cudaGetSymbolAddress((void**)&cs,    g_cs);
    cudaGetSymbolAddress((void**)&he,    g_he);
    cudaGetSymbolAddress((void**)&hs,    g_hs);

    __nv_bfloat16 *xbh, *xbl, *w1h, *w1l, *wxh, *wxl, *xch, *xcl;
    __half *wof, *ymf;
    cudaGetSymbolAddress((void**)&xbh, g_xbh);
    cudaGetSymbolAddress((void**)&xbl, g_xbl);
    cudaGetSymbolAddress((void**)&w1h, g_w1h);
    cudaGetSymbolAddress((void**)&w1l, g_w1l);
    cudaGetSymbolAddress((void**)&wxh, g_wxh);
    cudaGetSymbolAddress((void**)&wxl, g_wxl);
    cudaGetSymbolAddress((void**)&xch, g_xch);
    cudaGetSymbolAddress((void**)&xcl, g_xcl);
    cudaGetSymbolAddress((void**)&wof, g_wof);
    cudaGetSymbolAddress((void**)&ymf, g_ymf);

    // per-direction input pointers
    const float* in_w[2];  const float* conv_w[2]; const float* conv_b[2];
    const float* xproj_w[2]; const float* dt_w[2]; const float* dt_b[2];
    const float* A_log[2]; const float* Dp[2];     const float* out_w[2];
    for (int dir = 0; dir < 2; dir++) {
        in_w[dir]    = (const float*)d_in[1 + dir * 9 + 0];
        conv_w[dir]  = (const float*)d_in[1 + dir * 9 + 1];
        conv_b[dir]  = (const float*)d_in[1 + dir * 9 + 2];
        xproj_w[dir] = (const float*)d_in[1 + dir * 9 + 3];
        dt_w[dir]    = (const float*)d_in[1 + dir * 9 + 4];
        dt_b[dir]    = (const float*)d_in[1 + dir * 9 + 5];
        A_log[dir]   = (const float*)d_in[1 + dir * 9 + 6];
        Dp[dir]      = (const float*)d_in[1 + dir * 9 + 7];
        out_w[dir]   = (const float*)d_in[1 + dir * 9 + 8];
    }

    const long HID = (long)MROWS * DIM;
    const int NW = (E2 * DM / 4) + (64 * DI / 4) + (DM * DI / 4);

    // 1) fused residual copy + x bf16 split; weight conversions (both dirs)
    prep_x_kernel<<<(MROWS * DIM / 4 + 255) / 256, 256>>>(x, out + HID, xbh, xbl, MROWS * DIM / 4);
    split_weights_kernel<<<dim3((NW + 255) / 256, 2), 256>>>(
        in_w[0], in_w[1], xproj_w[0], xproj_w[1], out_w[0], out_w[1],
        w1h, w1l, wxh, wxl, wof);

    // 2) xz[dir] = x_dir @ in_w[dir]^T   (M=4096, N=2048, K=512), both dirs, 3-term bf16
    mma_gemm_kernel<128, 128, 64, 32, 3, 0><<<dim3(E2 / 128, MROWS / 128, 2), 256>>>(
        xbh, xbl, w1h, w1l, xz, DM, 1,
        /*lda*/ DIM, /*a_dstride*/ 0, /*acol0_step*/ DM, /*flip_is_dir*/ 1,
        /*ldb*/ DM, /*b_dstride*/ (long)E2 * DM,
        /*ldc*/ E2, /*c_dstride*/ (long)MROWS * E2, /*ccol0_step*/ 0, 0);

    // 3) conv + silu, both dirs
    conv_silu_kernel<<<dim3(DI / 256, LL / 8, 2 * BB), 256>>>(
        xz, conv_w[0], conv_w[1], conv_b[0], conv_b[1], xc, xch, xcl);

    // 4) dbc = xc @ xproj_w^T  (split-K=4), both dirs, 3-term bf16 + reduce
    mma_gemm_kernel<64, 64, 32, 32, 3, 0><<<dim3(1, MROWS / 64, 2 * KSPLIT), 128>>>(
        xch, xcl, wxh, wxl, part, DI / KSPLIT, KSPLIT,
        DI, (long)MROWS * DI, 0, 0,
        DI, (long)64 * DI,
        64, (long)KSPLIT * MROWS * 64, 0, (long)MROWS * 64);
    reduce_partials_kernel<<<(2 * MROWS * 64 / 4 + 255) / 256, 256>>>(part, dbc);

    // 5) delta, both dirs
    delta_kernel<<<dim3(DI / 256, MROWS / 4, 2), 256>>>(
        dbc, dt_w[0], dt_w[1], dt_b[0], dt_b[1], delta);

    // 6-8) chunked parallel scan, both dirs
    scan_pass1_kernel<<<dim3(NC, DI / 256, 2 * BB), 256>>>(
        delta, xc, dbc, A_log[0], A_log[1], cs, he);
    scan_fixup_kernel<<<(2 * BB * DI * DS) / 256, 256>>>(
        cs, he, A_log[0], A_log[1], hs);
    scan_pass3_kernel<<<dim3(NC, DI / 256, 2 * BB), 256>>>(
        delta, xc, dbc, A_log[0], A_log[1], hs, Dp[0], Dp[1], xz, ymf);

    // 9) hidden[:, :, dir*512:+512] = ym @ out_w^T  (M=4096, N=512, K=1024),
    //    both dirs, SINGLE fp16 term (output-adjacent, no error compounding)
    mma_gemm_kernel<128, 128, 64, 32, 1, 1><<<dim3(DM / 128, MROWS / 128, 2), 256>>>(
        (const __nv_bfloat16*)ymf, nullptr, (const __nv_bfloat16*)wof, nullptr, out, DI, 1,
        DI, (long)MROWS * DI, 0, 0,
        DI, (long)DM * DI,
        DIM, 0, DM, 0);
}

// round 7
// speedup vs baseline: 3.5469x; 1.1840x over previous
#include <cuda_runtime.h>
#include <cuda_bf16.h>
#include <cuda_fp16.h>
#include <cstdint>

// Problem constants
#define BB    2
#define LL    2048
#define DIM   1024
#define DM    512
#define DI    1024
#define E2    2048      // 2*DI
#define MROWS 4096      // BB*LL
#define DS    16        // D_STATE
#define DTR   32        // DT_RANK
#define NC    16        // scan chunks
#define LC    128       // chunk length (NC*LC == LL)
#define KSPLIT 4        // split-K factor for xproj GEMM

// ---------------- scratch (static device memory; no allocation allowed) ----------
__device__ float g_xz   [2][MROWS * E2];       // in-proj output (xh | z)
__device__ float g_xc   [2][MROWS * DI];       // conv+silu output (fp32 for scan)
__device__ float g_dbc  [2][MROWS * 64];       // x-proj output (dt|B|C)
__device__ float g_part [2][KSPLIT][MROWS * 64]; // split-K partials for xproj
__device__ float g_delta[2][MROWS * DI];       // softplus(dt @ dt_w^T + dt_b)
__device__ float g_cs   [2][BB * NC * DI];            // per-chunk sum of delta
__device__ float g_he   [2][BB * NC * DI * DS];       // chunk-local h_end
__device__ float g_hs   [2][BB * NC * DI * DS];       // chunk h_start (after fixup)

// fp16 single operands for GEMM1 (in-proj) and GEMM3 (out-proj)
__device__ __half g_xf  [MROWS * DIM];
__device__ __half g_w1f [2][E2 * DM];
__device__ __half g_wof [2][DM * DI];
__device__ __half g_ymf [2][MROWS * DI];

// bf16 hi/lo split operands for the scan-critical xproj GEMM
__device__ __nv_bfloat16 g_wxh [2][64 * DI];
__device__ __nv_bfloat16 g_wxl [2][64 * DI];
__device__ __nv_bfloat16 g_xch [2][MROWS * DI];
__device__ __nv_bfloat16 g_xcl [2][MROWS * DI];

// ---------------- helpers ----------------------------------------------------------
__device__ __forceinline__ void split2(float v, __nv_bfloat16& h, __nv_bfloat16& l) {
    h = __float2bfloat16(v);
    l = __float2bfloat16(v - __bfloat162float(h));
}

__device__ __forceinline__ void mma_bf16(float* c, const uint32_t* a, const uint32_t* b) {
    asm volatile(
        "mma.sync.aligned.m16n8k16.row.col.f32.bf16.bf16.f32 "
        "{%0,%1,%2,%3}, {%4,%5,%6,%7}, {%8,%9}, {%0,%1,%2,%3};\n"
        : "+f"(c[0]), "+f"(c[1]), "+f"(c[2]), "+f"(c[3])
        : "r"(a[0]), "r"(a[1]), "r"(a[2]), "r"(a[3]), "r"(b[0]), "r"(b[1]));
}

__device__ __forceinline__ void mma_f16(float* c, const uint32_t* a, const uint32_t* b) {
    asm volatile(
        "mma.sync.aligned.m16n8k16.row.col.f32.f16.f16.f32 "
        "{%0,%1,%2,%3}, {%4,%5,%6,%7}, {%8,%9}, {%0,%1,%2,%3};\n"
        : "+f"(c[0]), "+f"(c[1]), "+f"(c[2]), "+f"(c[3])
        : "r"(a[0]), "r"(a[1]), "r"(a[2]), "r"(a[3]), "r"(b[0]), "r"(b[1]));
}

__device__ __forceinline__ void ldsm_x4(uint32_t& r0, uint32_t& r1, uint32_t& r2, uint32_t& r3, uint32_t a) {
    asm volatile("ldmatrix.sync.aligned.m8n8.x4.shared.b16 {%0,%1,%2,%3}, [%4];"
                 : "=r"(r0), "=r"(r1), "=r"(r2), "=r"(r3) : "r"(a));
}

#define CPASYNC16(dst, src) asm volatile("cp.async.cg.shared.global [%0], [%1], 16;\n" :: "r"(dst), "l"(src))
#define CPCOMMIT()          asm volatile("cp.async.commit_group;\n")
#define CPWAIT1()           asm volatile("cp.async.wait_group 1;\n")

__device__ __forceinline__ uint32_t smem_u32(const void* p) {
    return (uint32_t)__cvta_generic_to_shared(p);
}

// ---------------- split fp32 -> bf16 hi/lo (vectorized float4) ---------------------
__device__ __forceinline__ void split_body(const float* __restrict__ in,
                                           __nv_bfloat16* __restrict__ hi,
                                           __nv_bfloat16* __restrict__ lo, int i)
{
    float4 v = reinterpret_cast<const float4*>(in)[i];
    float vv[4] = {v.x, v.y, v.z, v.w};
    __nv_bfloat16 h[4], l[4];
#pragma unroll
    for (int k = 0; k < 4; k++) split2(vv[k], h[k], l[k]);
    __nv_bfloat162* hp = reinterpret_cast<__nv_bfloat162*>(hi) + 2 * i;
    __nv_bfloat162* lp = reinterpret_cast<__nv_bfloat162*>(lo) + 2 * i;
    __nv_bfloat162 t;
    t.x = h[0]; t.y = h[1]; hp[0] = t;
    t.x = h[2]; t.y = h[3]; hp[1] = t;
    t.x = l[0]; t.y = l[1]; lp[0] = t;
    t.x = l[2]; t.y = l[3]; lp[1] = t;
}

// single fp16 conversion (vectorized)
__device__ __forceinline__ void half_body(const float* __restrict__ in,
                                          __half* __restrict__ o, int i)
{
    float4 v = reinterpret_cast<const float4*>(in)[i];
    __half2* op = reinterpret_cast<__half2*>(o) + 2 * i;
    op[0] = __floats2half2_rn(v.x, v.y);
    op[1] = __floats2half2_rn(v.z, v.w);
}

// Fused: residual copy + x -> fp16 conversion (x read once)
__global__ void prep_x_kernel(const float* __restrict__ x,
                              float* __restrict__ resid,
                              __half* __restrict__ xf, int n4)
{
    int i = blockIdx.x * 256 + threadIdx.x;
    if (i >= n4) return;
    float4 v = reinterpret_cast<const float4*>(x)[i];
    reinterpret_cast<float4*>(resid)[i] = v;
    __half2* op = reinterpret_cast<__half2*>(xf) + 2 * i;
    op[0] = __floats2half2_rn(v.x, v.y);
    op[1] = __floats2half2_rn(v.z, v.w);
}

// Batched per-direction weight conversions, both dirs, one launch.
// in_w -> fp16; xproj_w -> bf16 hi/lo; out_w -> fp16.
__global__ void split_weights_kernel(const float* __restrict__ w1a, const float* __restrict__ w1b,
                                     const float* __restrict__ wxa, const float* __restrict__ wxb,
                                     const float* __restrict__ woa, const float* __restrict__ wob,
                                     __half* __restrict__ w1f,
                                     __nv_bfloat16* __restrict__ wxh, __nv_bfloat16* __restrict__ wxl,
                                     __half* __restrict__ wof)
{
    const int N1 = E2 * DM / 4;
    const int N2 = 64 * DI / 4;
    const int N3 = DM * DI / 4;
    int dir = blockIdx.y;
    const float* w1 = dir ? w1b : w1a;
    const float* wx = dir ? wxb : wxa;
    const float* wo = dir ? wob : woa;
    int i = blockIdx.x * 256 + threadIdx.x;
    if (i < N1) { half_body(w1, w1f + (long)dir * E2 * DM, i); return; }
    i -= N1;
    if (i < N2) { split_body(wx, wxh + (long)dir * 64 * DI, wxl + (long)dir * 64 * DI, i); return; }
    i -= N2;
    if (i < N3) { half_body(wo, wof + (long)dir * DM * DI, i); }
}

// ---------------- tensor-core NT GEMM, ldmatrix + 3-stage cp.async -----------------
// TERMS=3: C = Ahi*Bhi + Ahi*Blo + Alo*Bhi (bf16 hi/lo).  TERMS=1: C = A*B (single).
// FP16=1 uses f16 mma, else bf16. Batched over blockIdx.z = dir*nks + kz.
template<int BM, int BN, int WM, int WN, int TERMS, int FP16>
__global__ void __launch_bounds__((BM / WM) * (BN / WN) * 32)
mma_gemm_kernel(const __nv_bfloat16* __restrict__ Ahi, const __nv_bfloat16* __restrict__ Alo,
                const __nv_bfloat16* __restrict__ Bhi, const __nv_bfloat16* __restrict__ Blo,
                float* __restrict__ C, int ksplit, int nks,
                int lda, long a_dstride, int acol0_step, int flip_is_dir,
                int ldb, long b_dstride,
                int ldc, long c_dstride, int ccol0_step, long csplit_stride)
{
    constexpr int THREADS = (BM / WM) * (BN / WN) * 32;
    constexpr int WM16 = WM / 16;
    constexpr int WN8  = WN / 8;
    constexpr int NCOMP = (TERMS == 1) ? 1 : 2;

    __shared__ __align__(16) uint8_t As[3 * NCOMP * BM * 32];   // [stage][comp][BM][32B]
    __shared__ __align__(16) uint8_t Bs[3 * NCOMP * BN * 32];

    const int tid  = threadIdx.x;
    const int bm0  = blockIdx.y * BM;
    const int bn0  = blockIdx.x * BN;
    const int z    = blockIdx.z;
    const int dir  = z / nks;
    const int kz   = z - dir * nks;
    const int kbeg = kz * ksplit;
    const int KT   = ksplit / 16;

    const __nv_bfloat16* Ahp = Ahi + (long)dir * a_dstride;
    const __nv_bfloat16* Alp = Alo ? Alo + (long)dir * a_dstride : nullptr;
    const __nv_bfloat16* Bhp = Bhi + (long)dir * b_dstride;
    const __nv_bfloat16* Blp = Blo ? Blo + (long)dir * b_dstride : nullptr;
    const int acol0 = dir * acol0_step;
    const int ccol0 = dir * ccol0_step;
    const int flip  = flip_is_dir ? dir : 0;
    C += (long)dir * c_dstride + (long)kz * csplit_stride;

    const int wid  = tid >> 5;
    const int lane = tid & 31;
    const int wm   = wid / (BN / WN);
    const int wn   = wid % (BN / WN);
    const int g    = lane >> 2;
    const int t    = lane & 3;

    float acc[WM16][WN8][4];
#pragma unroll
    for (int i = 0; i < WM16; i++)
#pragma unroll
        for (int j = 0; j < WN8; j++)
#pragma unroll
            for (int q = 0; q < 4; q++) acc[i][j][q] = 0.f;

    auto loadA = [&](int st, int k0) {
        for (int i = tid; i < BM * 2 * NCOMP; i += THREADS) {
            int comp = i / (BM * 2);
            int rem  = i - comp * BM * 2;
            int r = rem >> 1;
            int c = rem & 1;
            int mg = bm0 + r;
            int rowg = mg;
            if (flip) { int b = mg >> 11; int l = mg & 2047; rowg = (b << 11) + (2047 - l); }
            const __nv_bfloat16* src = (comp ? Alp : Ahp) + (long)rowg * lda + acol0 + k0 + c * 8;
            uint32_t dst = smem_u32(As + ((st * NCOMP + comp) * BM + r) * 32 + ((c ^ ((r >> 2) & 1)) << 4));
            CPASYNC16(dst, src);
        }
    };
    auto loadB = [&](int st, int k0) {
        for (int i = tid; i < BN * 2 * NCOMP; i += THREADS) {
            int comp = i / (BN * 2);
            int rem  = i - comp * BN * 2;
            int r = rem >> 1;
            int c = rem & 1;
            const __nv_bfloat16* src = (comp ? Blp : Bhp) + (long)(bn0 + r) * ldb + k0 + c * 8;
            uint32_t dst = smem_u32(Bs + ((st * NCOMP + comp) * BN + r) * 32 + ((c ^ ((r >> 2) & 1)) << 4));
            CPASYNC16(dst, src);
        }
    };

    const int a_tile   = lane >> 3;
    const int a_rowoff = ((a_tile & 1) << 3) + (lane & 7);
    const int a_chunk  = a_tile >> 1;
    const int b_rowoff = (((lane >> 4) & 1) << 3) + (lane & 7);
    const int b_chunk  = (lane >> 3) & 1;

    // prologue: stages 0 and 1
    loadA(0, kbeg); loadB(0, kbeg); CPCOMMIT();
    if (KT > 1) { loadA(1, kbeg + 16); loadB(1, kbeg + 16); }
    CPCOMMIT();

    for (int kt = 0; kt < KT; kt++) {
        CPWAIT1();
        __syncthreads();

        if (kt + 2 < KT) { loadA((kt + 2) % 3, kbeg + (kt + 2) * 16); loadB((kt + 2) % 3, kbeg + (kt + 2) * 16); }
        CPCOMMIT();

        const int st = kt % 3;
        const uint8_t* Ah = As + (st * NCOMP + 0) * BM * 32;
        const uint8_t* Bh = Bs + (st * NCOMP + 0) * BN * 32;
        const uint8_t* Al = As + (st * NCOMP + (NCOMP - 1)) * BM * 32;
        const uint8_t* Bl = Bs + (st * NCOMP + (NCOMP - 1)) * BN * 32;

        uint32_t ah[WM16][4], al[WM16][4], bh[WN8][2], bl[WN8][2];
#pragma unroll
        for (int i = 0; i < WM16; i++) {
            int r = wm * WM + i * 16 + a_rowoff;
            uint32_t off = r * 32 + (((a_chunk ^ ((r >> 2) & 1))) << 4);
            ldsm_x4(ah[i][0], ah[i][1], ah[i][2], ah[i][3], smem_u32(Ah + off));
            if (TERMS == 3) ldsm_x4(al[i][0], al[i][1], al[i][2], al[i][3], smem_u32(Al + off));
        }
#pragma unroll
        for (int jp = 0; jp < WN8 / 2; jp++) {
            int r = wn * WN + jp * 16 + b_rowoff;
            uint32_t off = r * 32 + (((b_chunk ^ ((r >> 2) & 1))) << 4);
            ldsm_x4(bh[2 * jp][0], bh[2 * jp][1], bh[2 * jp + 1][0], bh[2 * jp + 1][1], smem_u32(Bh + off));
            if (TERMS == 3) ldsm_x4(bl[2 * jp][0], bl[2 * jp][1], bl[2 * jp + 1][0], bl[2 * jp + 1][1], smem_u32(Bl + off));
        }
#pragma unroll
        for (int i = 0; i < WM16; i++)
#pragma unroll
            for (int j = 0; j < WN8; j++) {
                if (FP16) {
                    mma_f16(acc[i][j], ah[i], bh[j]);
                    if (TERMS == 3) { mma_f16(acc[i][j], ah[i], bl[j]); mma_f16(acc[i][j], al[i], bh[j]); }
                } else {
                    mma_bf16(acc[i][j], ah[i], bh[j]);
                    if (TERMS == 3) { mma_bf16(acc[i][j], ah[i], bl[j]); mma_bf16(acc[i][j], al[i], bh[j]); }
                }
            }
    }

    // epilogue: fp32 direct store (cols 2t,2t+1 contiguous -> float2)
#pragma unroll
    for (int i = 0; i < WM16; i++) {
#pragma unroll
        for (int j = 0; j < WN8; j++) {
            int r  = bm0 + wm * WM + i * 16 + g;
            int n0 = bn0 + ccol0 + wn * WN + j * 8 + 2 * t;
            float2 v0 = make_float2(acc[i][j][0], acc[i][j][1]);
            float2 v1 = make_float2(acc[i][j][2], acc[i][j][3]);
            *reinterpret_cast<float2*>(&C[(long)r * ldc + n0])       = v0;
            *reinterpret_cast<float2*>(&C[(long)(r + 8) * ldc + n0]) = v1;
        }
    }
}

// ---------------- split-K reduction: dbc[dir] = sum_z part[dir][z], both dirs ------
__global__ void reduce_partials_kernel(const float* __restrict__ part, float* __restrict__ dbc)
{
    const int n4 = MROWS * 64 / 4;             // per-dir float4 count
    int i = blockIdx.x * 256 + threadIdx.x;    // over 2*n4
    if (i >= 2 * n4) return;
    int dir = i / n4;
    int j = i - dir * n4;
    const float* p = part + (long)dir * KSPLIT * MROWS * 64;
    float4 a = reinterpret_cast<const float4*>(p)[j];
#pragma unroll
    for (int z = 1; z < KSPLIT; z++) {
        float4 b = reinterpret_cast<const float4*>(p + (long)z * MROWS * 64)[j];
        a.x += b.x; a.y += b.y; a.z += b.z; a.w += b.w;
    }
    reinterpret_cast<float4*>(dbc + (long)dir * MROWS * 64)[j] = a;
}

// ---------------- depthwise causal conv(4) + silu (+ bf16 split out), batched ------
__global__ void conv_silu_kernel(const float* __restrict__ xz_base,
                                 const float* __restrict__ cwa, const float* __restrict__ cwb,
                                 const float* __restrict__ cba, const float* __restrict__ cbb,
                                 float* __restrict__ xc_base,
                                 __nv_bfloat16* __restrict__ xch_base,
                                 __nv_bfloat16* __restrict__ xcl_base)
{
    int c  = blockIdx.x * blockDim.x + threadIdx.x;   // channel in [0,DI)
    int l0 = blockIdx.y * 8;
    int zb = blockIdx.z;
    int dir = zb >> 1;
    int b   = zb & 1;

    const float* cw = dir ? cwb : cwa;
    const float* cb = dir ? cbb : cba;
    const float* xz = xz_base + (long)dir * MROWS * E2;
    float* xc = xc_base + (long)dir * MROWS * DI;
    __nv_bfloat16* xch = xch_base + (long)dir * MROWS * DI;
    __nv_bfloat16* xcl = xcl_base + (long)dir * MROWS * DI;

    float w0 = cw[c * 4 + 0], w1 = cw[c * 4 + 1], w2 = cw[c * 4 + 2], w3 = cw[c * 4 + 3];
    float bias = cb[c];

    float v[11];
#pragma unroll
    for (int j = 0; j < 11; j++) {
        int l = l0 - 3 + j;
        v[j] = (l >= 0) ? xz[(long)(b * LL + l) * E2 + c] : 0.f;
    }
#pragma unroll
    for (int i = 0; i < 8; i++) {
        float a = v[i] * w0 + v[i + 1] * w1 + v[i + 2] * w2 + v[i + 3] * w3 + bias;
        float s = a / (1.f + __expf(-a));   // silu
        long idx = (long)(b * LL + l0 + i) * DI + c;
        xc[idx] = s;
        __nv_bfloat16 h, l2;
        split2(s, h, l2);
        xch[idx] = h;
        xcl[idx] = l2;
    }
}

// ---------------- delta = softplus(dt @ dt_w^T + dt_b), batched --------------------
__global__ void delta_kernel(const float* __restrict__ dbc_base,
                             const float* __restrict__ dwa, const float* __restrict__ dwb,
                             const float* __restrict__ dba, const float* __restrict__ dbb,
                             float* __restrict__ delta_base)
{
    int d   = blockIdx.x * 256 + threadIdx.x;  // [0,DI)
    int m0  = blockIdx.y * 4;
    int dir = blockIdx.z;

    const float* dt_w = dir ? dwb : dwa;
    const float* dt_b = dir ? dbb : dba;
    const float* dbc = dbc_base + (long)dir * MROWS * 64;
    float* delta = delta_base + (long)dir * MROWS * DI;

    float w[DTR];
    const float4* w4 = reinterpret_cast<const float4*>(dt_w + (long)d * DTR);
#pragma unroll
    for (int r = 0; r < DTR / 4; r++) {
        float4 v = w4[r];
        w[4 * r + 0] = v.x; w[4 * r + 1] = v.y; w[4 * r + 2] = v.z; w[4 * r + 3] = v.w;
    }
    float bias = dt_b[d];

#pragma unroll
    for (int mi = 0; mi < 4; mi++) {
        const float* row = dbc + (long)(m0 + mi) * 64;
        float acc = bias;
#pragma unroll
        for (int r = 0; r < DTR; r++) acc = fmaf(row[r], w[r], acc);
        float sp = (acc > 20.f) ? acc : log1pf(__expf(acc));
        delta[(long)(m0 + mi) * DI + d] = sp;
    }
}

// ---------------- scan pass1: chunk-local scan from h=0, batched -------------------
__global__ void scan_pass1_kernel(const float* __restrict__ delta_base,
                                  const float* __restrict__ xc_base,
                                  const float* __restrict__ dbc_base,
                                  const float* __restrict__ Aa_, const float* __restrict__ Ab_,
                                  float* __restrict__ cs_base,
                                  float* __restrict__ he_base)
{
    __shared__ float sB[LC][DS];
    int chunk = blockIdx.x;
    int d     = blockIdx.y * 256 + threadIdx.x;
    int zb    = blockIdx.z;
    int dir   = zb >> 1;
    int b     = zb & 1;
    int m0    = b * LL + chunk * LC;

    const float* A_log = dir ? Ab_ : Aa_;
    const float* delta = delta_base + (long)dir * MROWS * DI;
    const float* xc    = xc_base    + (long)dir * MROWS * DI;
    const float* dbc   = dbc_base   + (long)dir * MROWS * 64;
    float* cs = cs_base + (long)dir * BB * NC * DI;
    float* he = he_base + (long)dir * BB * NC * DI * DS;

    const float* dbc0 = dbc + (long)m0 * 64;
    for (int i = threadIdx.x; i < LC * DS; i += 256) {
        int tt = i >> 4, s = i & 15;
        sB[tt][s] = dbc0[tt * 64 + 32 + s];
    }
    __syncthreads();

    float Aa[DS];
#pragma unroll
    for (int s = 0; s < DS; s++) Aa[s] = -__expf(A_log[d * DS + s]);
    float a0 = Aa[0];
    bool fast = true;
#pragma unroll
    for (int s = 1; s < DS; s++) fast = fast && (fabsf(Aa[s] - (s + 1) * a0) < 1e-4f * fabsf(Aa[s]));

    float h[DS];
#pragma unroll
    for (int s = 0; s < DS; s++) h[s] = 0.f;
    float S = 0.f;

    if (fast) {
        for (int tt = 0; tt < LC; tt++) {
            int m = m0 + tt;
            float dlt = delta[(long)m * DI + d];
            float xcv = xc[(long)m * DI + d];
            S += dlt;
            float du = dlt * xcv;
            float e1 = __expf(dlt * a0);
            float p = e1;
#pragma unroll
            for (int s = 0; s < DS; s++) {
                h[s] = fmaf(h[s], p, du * sB[tt][s]);
                p *= e1;
            }
        }
    } else {
        for (int tt = 0; tt < LC; tt++) {
            int m = m0 + tt;
            float dlt = delta[(long)m * DI + d];
            float xcv = xc[(long)m * DI + d];
            S += dlt;
            float du = dlt * xcv;
#pragma unroll
            for (int s = 0; s < DS; s++) {
                float da = __expf(dlt * Aa[s]);
                h[s] = fmaf(h[s], da, du * sB[tt][s]);
            }
        }
    }

    cs[(long)(b * NC + chunk) * DI + d] = S;
    float* hout = he + ((long)(b * NC + chunk) * DI + d) * DS;
#pragma unroll
    for (int s = 0; s < DS; s++) hout[s] = h[s];
}

// ---------------- scan fixup: sequential over the 16 chunks, batched ---------------
__global__ void scan_fixup_kernel(const float* __restrict__ cs_base,
                                  const float* __restrict__ he_base,
                                  const float* __restrict__ Aa_, const float* __restrict__ Ab_,
                                  float* __restrict__ hs_base)
{
    int idx = blockIdx.x * 256 + threadIdx.x;      // 2*BB*DI*DS threads
    int s = idx & 15;
    int d = (idx >> 4) & (DI - 1);
    int b = (idx >> 14) & 1;
    int dir = idx >> 15;

    const float* A_log = dir ? Ab_ : Aa_;
    const float* cs = cs_base + (long)dir * BB * NC * DI;
    const float* he = he_base + (long)dir * BB * NC * DI * DS;
    float* hs = hs_base + (long)dir * BB * NC * DI * DS;

    float A = -__expf(A_log[d * DS + s]);
    float h = 0.f;
    for (int c = 0; c < NC; c++) {
        long base = ((long)(b * NC + c) * DI + d) * DS + s;
        hs[base] = h;
        float S = cs[(long)(b * NC + c) * DI + d];
        h = __expf(A * S) * h + he[base];
    }
}

// ---------------- scan pass3: replay with h_start, emit gated y (single fp16) ------
__global__ void scan_pass3_kernel(const float* __restrict__ delta_base,
                                  const float* __restrict__ xc_base,
                                  const float* __restrict__ dbc_base,
                                  const float* __restrict__ Aa_, const float* __restrict__ Ab_,
                                  const float* __restrict__ hs_base,
                                  const float* __restrict__ Da_, const float* __restrict__ Db_,
                                  const float* __restrict__ xz_base,
                                  __half* __restrict__ ymf_base)
{
    __shared__ float sB[LC][DS];
    __shared__ float sC[LC][DS];
    int chunk = blockIdx.x;
    int d     = blockIdx.y * 256 + threadIdx.x;
    int zb    = blockIdx.z;
    int dir   = zb >> 1;
    int b     = zb & 1;
    int m0    = b * LL + chunk * LC;

    const float* A_log = dir ? Ab_ : Aa_;
    const float* Dp    = dir ? Db_ : Da_;
    const float* delta = delta_base + (long)dir * MROWS * DI;
    const float* xc    = xc_base    + (long)dir * MROWS * DI;
    const float* dbc   = dbc_base   + (long)dir * MROWS * 64;
    const float* hs    = hs_base    + (long)dir * BB * NC * DI * DS;
    const float* xz    = xz_base    + (long)dir * MROWS * E2;
    __half* ymf = ymf_base + (long)dir * MROWS * DI;

    const float* dbc0 = dbc + (long)m0 * 64;
    for (int i = threadIdx.x; i < LC * DS; i += 256) {
        int tt = i >> 4, s = i & 15;
        sB[tt][s] = dbc0[tt * 64 + 32 + s];
        sC[tt][s] = dbc0[tt * 64 + 48 + s];
    }
    __syncthreads();

    float Aa[DS];
#pragma unroll
    for (int s = 0; s < DS; s++) Aa[s] = -__expf(A_log[d * DS + s]);
    float a0 = Aa[0];
    bool fast = true;
#pragma unroll
    for (int s = 1; s < DS; s++) fast = fast && (fabsf(Aa[s] - (s + 1) * a0) < 1e-4f * fabsf(Aa[s]));

    float h[DS];
    const float* hin = hs + ((long)(b * NC + chunk) * DI + d) * DS;
#pragma unroll
    for (int s = 0; s < DS; s++) h[s] = hin[s];

    float Dv = Dp[d];

    for (int tt = 0; tt < LC; tt++) {
        int m = m0 + tt;
        float dlt = delta[(long)m * DI + d];
        float xcv = xc[(long)m * DI + d];
        float du = dlt * xcv;
        float y = 0.f;
        if (fast) {
            float e1 = __expf(dlt * a0);
            float p = e1;
#pragma unroll
            for (int s = 0; s < DS; s++) {
                h[s] = fmaf(h[s], p, du * sB[tt][s]);
                y = fmaf(h[s], sC[tt][s], y);
                p *= e1;
            }
        } else {
#pragma unroll
            for (int s = 0; s < DS; s++) {
                float da = __expf(dlt * Aa[s]);
                h[s] = fmaf(h[s], da, du * sB[tt][s]);
                y = fmaf(h[s], sC[tt][s], y);
            }
        }
        float z = xz[(long)m * E2 + DI + d];
        float sil = z / (1.f + __expf(-z));
        float out = (y + xcv * Dv) * sil;
        ymf[(long)m * DI + d] = __float2half(out);
    }
}

// ---------------- host launcher ---------------------------------------------------
extern "C" void kernel_launch(void* const* d_in, const int* in_sizes, int n_in,
                              void* d_out, int out_size)
{
    const float* x = (const float*)d_in[0];
    float* out = (float*)d_out;

    float *xz, *xc, *dbc, *part, *delta, *cs, *he, *hs;
    cudaGetSymbolAddress((void**)&xz,    g_xz);
    cudaGetSymbolAddress((void**)&xc,    g_xc);
    cudaGetSymbolAddress((void**)&dbc,   g_dbc);
    cudaGetSymbolAddress((void**)&part,  g_part);
    cudaGetSymbolAddress((void**)&delta, g_delta);
    cudaGetSymbolAddress((void**)&cs,    g_cs);
    cudaGetSymbolAddress((void**)&he,    g_he);
    cudaGetSymbolAddress((void**)&hs,    g_hs);

    __nv_bfloat16 *wxh, *wxl, *xch, *xcl;
    __half *xf, *w1f, *wof, *ymf;
    cudaGetSymbolAddress((void**)&wxh, g_wxh);
    cudaGetSymbolAddress((void**)&wxl, g_wxl);
    cudaGetSymbolAddress((void**)&xch, g_xch);
    cudaGetSymbolAddress((void**)&xcl, g_xcl);
    cudaGetSymbolAddress((void**)&xf,  g_xf);
    cudaGetSymbolAddress((void**)&w1f, g_w1f);
    cudaGetSymbolAddress((void**)&wof, g_wof);
    cudaGetSymbolAddress((void**)&ymf, g_ymf);

    // per-direction input pointers
    const float* in_w[2];  const float* conv_w[2]; const float* conv_b[2];
    const float* xproj_w[2]; const float* dt_w[2]; const float* dt_b[2];
    const float* A_log[2]; const float* Dp[2];     const float* out_w[2];
    for (int dir = 0; dir < 2; dir++) {
        in_w[dir]    = (const float*)d_in[1 + dir * 9 + 0];
        conv_w[dir]  = (const float*)d_in[1 + dir * 9 + 1];
        conv_b[dir]  = (const float*)d_in[1 + dir * 9 + 2];
        xproj_w[dir] = (const float*)d_in[1 + dir * 9 + 3];
        dt_w[dir]    = (const float*)d_in[1 + dir * 9 + 4];
        dt_b[dir]    = (const float*)d_in[1 + dir * 9 + 5];
        A_log[dir]   = (const float*)d_in[1 + dir * 9 + 6];
        Dp[dir]      = (const float*)d_in[1 + dir * 9 + 7];
        out_w[dir]   = (const float*)d_in[1 + dir * 9 + 8];
    }

    const long HID = (long)MROWS * DIM;
    const int NW = (E2 * DM / 4) + (64 * DI / 4) + (DM * DI / 4);

    // 1) fused residual copy + x fp16; weight conversions (both dirs)
    prep_x_kernel<<<(MROWS * DIM / 4 + 255) / 256, 256>>>(x, out + HID, xf, MROWS * DIM / 4);
    split_weights_kernel<<<dim3((NW + 255) / 256, 2), 256>>>(
        in_w[0], in_w[1], xproj_w[0], xproj_w[1], out_w[0], out_w[1],
        w1f, wxh, wxl, wof);

    // 2) xz[dir] = x_dir @ in_w[dir]^T  (M=4096, N=2048, K=512), both dirs, single fp16
    mma_gemm_kernel<128, 128, 64, 32, 1, 1><<<dim3(E2 / 128, MROWS / 128, 2), 256>>>(
        (const __nv_bfloat16*)xf, nullptr, (const __nv_bfloat16*)w1f, nullptr, xz, DM, 1,
        /*lda*/ DIM, /*a_dstride*/ 0, /*acol0_step*/ DM, /*flip_is_dir*/ 1,
        /*ldb*/ DM, /*b_dstride*/ (long)E2 * DM,
        /*ldc*/ E2, /*c_dstride*/ (long)MROWS * E2, /*ccol0_step*/ 0, 0);

    // 3) conv + silu, both dirs
    conv_silu_kernel<<<dim3(DI / 256, LL / 8, 2 * BB), 256>>>(
        xz, conv_w[0], conv_w[1], conv_b[0], conv_b[1], xc, xch, xcl);

    // 4) dbc = xc @ xproj_w^T  (split-K=4), both dirs, 3-term bf16 + reduce
    mma_gemm_kernel<64, 64, 32, 32, 3, 0><<<dim3(1, MROWS / 64, 2 * KSPLIT), 128>>>(
        xch, xcl, wxh, wxl, part, DI / KSPLIT, KSPLIT,
        DI, (long)MROWS * DI, 0, 0,
        DI, (long)64 * DI,
        64, (long)KSPLIT * MROWS * 64, 0, (long)MROWS * 64);
    reduce_partials_kernel<<<(2 * MROWS * 64 / 4 + 255) / 256, 256>>>(part, dbc);

    // 5) delta, both dirs
    delta_kernel<<<dim3(DI / 256, MROWS / 4, 2), 256>>>(
        dbc, dt_w[0], dt_w[1], dt_b[0], dt_b[1], delta);

    // 6-8) chunked parallel scan, both dirs
    scan_pass1_kernel<<<dim3(NC, DI / 256, 2 * BB), 256>>>(
        delta, xc, dbc, A_log[0], A_log[1], cs, he);
    scan_fixup_kernel<<<(2 * BB * DI * DS) / 256, 256>>>(
        cs, he, A_log[0], A_log[1], hs);
    scan_pass3_kernel<<<dim3(NC, DI / 256, 2 * BB), 256>>>(
        delta, xc, dbc, A_log[0], A_log[1], hs, Dp[0], Dp[1], xz, ymf);

    // 9) hidden[:, :, dir*512:+512] = ym @ out_w^T  (M=4096, N=512, K=1024),
    //    both dirs, single fp16
    mma_gemm_kernel<128, 128, 64, 32, 1, 1><<<dim3(DM / 128, MROWS / 128, 2), 256>>>(
        (const __nv_bfloat16*)ymf, nullptr, (const __nv_bfloat16*)wof, nullptr, out, DI, 1,
        DI, (long)MROWS * DI, 0, 0,
        DI, (long)DM * DI,
        DIM, 0, DM, 0);
}